// round 5
// baseline (speedup 1.0000x reference)
#include <cuda_runtime.h>
#include <math.h>

#define LL 768
#define CS 256
#define CZ 128
#define NH 8
#define FEAT 544
#define ATTN_OFF (LL*CS)

__device__ float g_sln[LL*CS];
__device__ float g_q[LL*CS];
__device__ float g_k[LL*CS];
__device__ float g_v[LL*CS];
__device__ float g_kt[CS*LL];            // [c][j]
__device__ float g_qpl[LL*96];
__device__ float g_kpl[LL*96];
__device__ float g_vpl[LL*192];
__device__ float g_qpg[LL*96];           // [i][h*12+pp]
__device__ float g_kpgt[96*LL];          // [(h*12+pp)][j]
__device__ float g_vpg[LL*192];          // [j][h*24+pp]
__device__ float g_qn[LL*NH];
__device__ float g_knt[NH*LL];
__device__ float g_pb[(long)NH*LL*LL];   // [h][i][j]
__device__ float g_pv[(long)LL*LL*32];   // [pair][h*4+d]
__device__ float g_feat[LL*FEAT];
__device__ float g_ptg[LL*192];
__device__ float g_T1[40];
__device__ float g_T0[40];

__device__ __forceinline__ unsigned long long pk2(float lo, float hi){
    unsigned long long r; asm("mov.b64 %0,{%1,%2};":"=l"(r):"f"(lo),"f"(hi)); return r;
}
__device__ __forceinline__ void fma2(unsigned long long &d, unsigned long long a, unsigned long long b){
    asm("fma.rn.f32x2 %0, %1, %2, %0;" : "+l"(d) : "l"(a), "l"(b));
}
__device__ __forceinline__ float2 upk2(unsigned long long v){
    float2 r; asm("mov.b64 {%0,%1},%2;":"=f"(r.x),"=f"(r.y):"l"(v)); return r;
}

// ---- LN of s ----
__global__ __launch_bounds__(256) void k_ln_s(const float* __restrict__ s,
                                              const float* __restrict__ w,
                                              const float* __restrict__ b){
    int i = blockIdx.x, t = threadIdx.x;
    float x = s[i*CS + t];
    __shared__ float sh[8]; __shared__ float s_m, s_r;
    float v = x;
    #pragma unroll
    for (int o=16;o;o>>=1) v += __shfl_xor_sync(~0u,v,o);
    if ((t&31)==0) sh[t>>5]=v;
    __syncthreads();
    if (t==0){ float u=0; for(int kk=0;kk<8;kk++)u+=sh[kk]; s_m=u*(1.f/256.f); }
    __syncthreads();
    float d = x - s_m; v = d*d;
    #pragma unroll
    for (int o=16;o;o>>=1) v += __shfl_xor_sync(~0u,v,o);
    if ((t&31)==0) sh[t>>5]=v;
    __syncthreads();
    if (t==0){ float u=0; for(int kk=0;kk<8;kk++)u+=sh[kk]; s_r=rsqrtf(u*(1.f/256.f)+1e-5f); }
    __syncthreads();
    g_sln[i*CS+t] = d*s_r*w[t] + b[t];
}

// ---- generic tiled SGEMM: C[M,N] = A[M,K] @ W[K,N] (+bias)(*mask) ----
__global__ __launch_bounds__(256) void k_sgemm(const float* __restrict__ A,
                                               const float* __restrict__ W,
                                               const float* __restrict__ bias,
                                               const float* __restrict__ msk,
                                               float* __restrict__ Cm,
                                               int M, int N, int K){
    __shared__ float As[16][65], Bs[16][65];
    int bx=blockIdx.x, by=blockIdx.y, tid=threadIdx.x;
    int tx=tid&15, ty=tid>>4;
    int m_base=by*64+ty*4, n_base=bx*64+tx*4;
    float acc[4][4];
    #pragma unroll
    for(int u=0;u<4;u++)
        #pragma unroll
        for(int w2=0;w2<4;w2++) acc[u][w2]=0.f;
    for (int k0=0;k0<K;k0+=16){
        for (int l=tid;l<1024;l+=256){
            int mm=l>>4, kk=l&15, gm=by*64+mm, gk=k0+kk;
            As[kk][mm] = (gm<M && gk<K) ? A[(long)gm*K+gk] : 0.f;
        }
        for (int l=tid;l<1024;l+=256){
            int nn=l&63, kk=l>>6, gn=bx*64+nn, gk=k0+kk;
            Bs[kk][nn] = (gn<N && gk<K) ? W[(long)gk*N+gn] : 0.f;
        }
        __syncthreads();
        #pragma unroll
        for(int kk=0;kk<16;kk++){
            float a[4], bb[4];
            #pragma unroll
            for(int u=0;u<4;u++) a[u]=As[kk][ty*4+u];
            #pragma unroll
            for(int u=0;u<4;u++) bb[u]=Bs[kk][tx*4+u];
            #pragma unroll
            for(int u=0;u<4;u++)
                #pragma unroll
                for(int w2=0;w2<4;w2++) acc[u][w2]+=a[u]*bb[w2];
        }
        __syncthreads();
    }
    #pragma unroll
    for(int u=0;u<4;u++){
        int gm=m_base+u; if(gm>=M) continue;
        float mv = msk?msk[gm]:1.f;
        #pragma unroll
        for(int w2=0;w2<4;w2++){
            int gn=n_base+w2; if(gn>=N) continue;
            float vv=acc[u][w2]; if(bias) vv+=bias[gn];
            Cm[(long)gm*N+gn]=vv*mv;
        }
    }
}

// ---- transpose k -> [c][j] ----
__global__ __launch_bounds__(256) void k_transpose_k(){
    __shared__ float tile[32][33];
    int c0=blockIdx.x*32, j0=blockIdx.y*32;
    int tx=threadIdx.x&31, ty=threadIdx.x>>5;
    for(int r=ty;r<32;r+=8) tile[r][tx]=g_k[(j0+r)*CS+c0+tx];
    __syncthreads();
    for(int r=ty;r<32;r+=8) g_kt[(c0+r)*LL+j0+tx]=tile[tx][r];
}

// ---- rigid transform of points + norms ----
__global__ __launch_bounds__(128) void k_transform(const float* __restrict__ R,
                                                   const float* __restrict__ t){
    int i=blockIdx.x, tid=threadIdx.x;
    __shared__ float Rl[9], tl[3];
    if(tid<9) Rl[tid]=R[i*9+tid];
    if(tid<3) tl[tid]=t[i*3+tid];
    __syncthreads();
    if (tid<32){
        float p0=g_qpl[i*96+tid*3], p1=g_qpl[i*96+tid*3+1], p2=g_qpl[i*96+tid*3+2];
        float gx=Rl[0]*p0+Rl[1]*p1+Rl[2]*p2+tl[0];
        float gy=Rl[3]*p0+Rl[4]*p1+Rl[5]*p2+tl[1];
        float gz=Rl[6]*p0+Rl[7]*p1+Rl[8]*p2+tl[2];
        g_qpg[i*96+tid*3]=gx; g_qpg[i*96+tid*3+1]=gy; g_qpg[i*96+tid*3+2]=gz;
        float sq=gx*gx+gy*gy+gz*gz;
        sq += __shfl_xor_sync(~0u,sq,1); sq += __shfl_xor_sync(~0u,sq,2);
        if((tid&3)==0) g_qn[i*NH+(tid>>2)]=sq;
    } else if (tid<64){
        int idx=tid-32;
        float p0=g_kpl[i*96+idx*3], p1=g_kpl[i*96+idx*3+1], p2=g_kpl[i*96+idx*3+2];
        float gx=Rl[0]*p0+Rl[1]*p1+Rl[2]*p2+tl[0];
        float gy=Rl[3]*p0+Rl[4]*p1+Rl[5]*p2+tl[1];
        float gz=Rl[6]*p0+Rl[7]*p1+Rl[8]*p2+tl[2];
        g_kpgt[(idx*3+0)*LL+i]=gx; g_kpgt[(idx*3+1)*LL+i]=gy; g_kpgt[(idx*3+2)*LL+i]=gz;
        float sq=gx*gx+gy*gy+gz*gz;
        sq += __shfl_xor_sync(~0u,sq,1); sq += __shfl_xor_sync(~0u,sq,2);
        if((idx&3)==0) g_knt[(idx>>2)*LL+i]=sq;
    } else {
        int idx=tid-64;
        float p0=g_vpl[i*192+idx*3], p1=g_vpl[i*192+idx*3+1], p2=g_vpl[i*192+idx*3+2];
        g_vpg[i*192+idx*3+0]=Rl[0]*p0+Rl[1]*p1+Rl[2]*p2+tl[0];
        g_vpg[i*192+idx*3+1]=Rl[3]*p0+Rl[4]*p1+Rl[5]*p2+tl[1];
        g_vpg[i*192+idx*3+2]=Rl[6]*p0+Rl[7]*p1+Rl[8]*p2+tl[2];
    }
}

// ---- premix LN-fold epilogue constants ----
__global__ void k_premix(const float* __restrict__ lnw, const float* __restrict__ lnb,
                         const float* __restrict__ Wpb, const float* __restrict__ Wpo){
    int n=threadIdx.x; if(n>=40) return;
    float t1=0.f, t0=0.f;
    for(int c=0;c<CZ;c++){
        float wv = (n<8) ? Wpb[c*8+n] : Wpo[c*32+n-8];
        t1 += lnw[c]*wv; t0 += lnb[c]*wv;
    }
    g_T1[n]=t1; g_T0[n]=t0;
}

// ---- z pass: LN folded, z read once -> pair_bias + pair_v ----
__global__ __launch_bounds__(256) void k_zpass(const float* __restrict__ z,
                                               const float* __restrict__ lnw,
                                               const float* __restrict__ Wpb,
                                               const float* __restrict__ Wpo){
    __shared__ float Zs[16][129];
    __shared__ unsigned long long Ws[16][20];   // 40 cols as 20 f32x2
    __shared__ float Os[128][41];
    __shared__ float s_mean[128], s_rstd[128], s_lnw[128], T1s[40], T0s[40];
    int tid=threadIdx.x;
    long pair0=(long)blockIdx.x*128;
    if(tid<128) s_lnw[tid]=lnw[tid];
    if(tid<40){ T1s[tid]=g_T1[tid]; T0s[tid]=g_T0[tid]; }
    __syncthreads();

    int tx=tid&63, ty=tid>>6;
    unsigned long long acc2[2][5];
    #pragma unroll
    for(int m=0;m<2;m++)
        #pragma unroll
        for(int n=0;n<5;n++) acc2[m][n]=0ull;

    float sum0=0.f,sq0=0.f,sum1=0.f,sq1=0.f;
    int rA=tid>>2, kq=tid&3;

    for(int k0=0;k0<CZ;k0+=16){
        float4 v4 = *(const float4*)&z[(pair0+rA)*CZ + k0 + kq*4];
        sum0 += v4.x+v4.y+v4.z+v4.w;
        sq0  += v4.x*v4.x+v4.y*v4.y+v4.z*v4.z+v4.w*v4.w;
        Zs[kq*4+0][rA]=v4.x; Zs[kq*4+1][rA]=v4.y; Zs[kq*4+2][rA]=v4.z; Zs[kq*4+3][rA]=v4.w;
        int rB=rA+64;
        float4 w4 = *(const float4*)&z[(pair0+rB)*CZ + k0 + kq*4];
        sum1 += w4.x+w4.y+w4.z+w4.w;
        sq1  += w4.x*w4.x+w4.y*w4.y+w4.z*w4.z+w4.w*w4.w;
        Zs[kq*4+0][rB]=w4.x; Zs[kq*4+1][rB]=w4.y; Zs[kq*4+2][rB]=w4.z; Zs[kq*4+3][rB]=w4.w;
        // stage weights pre-packed, lnw folded
        for(int l=tid;l<320;l+=256){
            int kk=l/20, np=l%20, n=np*2, c=k0+kk;
            float w0 = s_lnw[c] * ((n<8)   ? Wpb[c*8+n]     : Wpo[c*32+n-8]);
            float w1 = s_lnw[c] * ((n+1<8) ? Wpb[c*8+n+1]   : Wpo[c*32+n-7]);
            Ws[kk][np]=pk2(w0,w1);
        }
        __syncthreads();
        #pragma unroll
        for(int kk=0;kk<16;kk++){
            float z0=Zs[kk][tx], z1=Zs[kk][tx+64];
            unsigned long long z20=pk2(z0,z0), z21=pk2(z1,z1);
            const unsigned long long* wrow = &Ws[kk][ty*5];
            #pragma unroll
            for(int nn=0;nn<5;nn++){
                unsigned long long wp=wrow[nn];
                fma2(acc2[0][nn],z20,wp);
                fma2(acc2[1][nn],z21,wp);
            }
        }
        __syncthreads();
    }
    sum0+=__shfl_xor_sync(~0u,sum0,1); sum0+=__shfl_xor_sync(~0u,sum0,2);
    sq0 +=__shfl_xor_sync(~0u,sq0,1);  sq0 +=__shfl_xor_sync(~0u,sq0,2);
    sum1+=__shfl_xor_sync(~0u,sum1,1); sum1+=__shfl_xor_sync(~0u,sum1,2);
    sq1 +=__shfl_xor_sync(~0u,sq1,1);  sq1 +=__shfl_xor_sync(~0u,sq1,2);
    if((tid&3)==0){
        int r=tid>>2;
        float m=sum0*(1.f/128.f);
        s_mean[r]=m; s_rstd[r]=rsqrtf(sq0*(1.f/128.f)-m*m+1e-5f);
        m=sum1*(1.f/128.f);
        s_mean[r+64]=m; s_rstd[r+64]=rsqrtf(sq1*(1.f/128.f)-m*m+1e-5f);
    }
    __syncthreads();
    #pragma unroll
    for(int m=0;m<2;m++){
        int r=tx+m*64;
        float rs=s_rstd[r], mn=s_mean[r];
        #pragma unroll
        for(int nn=0;nn<5;nn++){
            float2 a=upk2(acc2[m][nn]);
            int n=ty*10+nn*2;
            Os[r][n]  =rs*(a.x-mn*T1s[n])  +T0s[n];
            Os[r][n+1]=rs*(a.y-mn*T1s[n+1])+T0s[n+1];
        }
    }
    __syncthreads();
    for(int l=tid;l<1024;l+=256){
        int hh=l>>7, r=l&127;
        long p=pair0+r; int i=(int)(p/LL), j=(int)(p%LL);
        g_pb[((long)hh*LL+i)*LL+j]=Os[r][hh];
    }
    for(int l=tid;l<4096;l+=256){
        int r=l>>5, o=l&31;
        g_pv[(pair0+r)*32+o]=Os[r][8+o];
    }
}

// ---- fused logits + softmax -> attn (direct to d_out) ----
__global__ __launch_bounds__(256) void k_logits_softmax(const float* __restrict__ mask,
                                                        const float* __restrict__ pweights,
                                                        float* __restrict__ attn){
    int h=blockIdx.y, i0=blockIdx.x*4, tid=threadIdx.x;
    __shared__ float qv[4][32], qp[4][12], qnv[4], mi[4], red[8][4], bmax[4], brcp[4], s_pw;
    if(tid<128){ int ii=tid>>5, c=tid&31; qv[ii][c]=g_q[(i0+ii)*CS+h*32+c]; }
    else if(tid<176){ int l=tid-128, ii=l/12, pp=l%12; qp[ii][pp]=g_qpg[(i0+ii)*96+h*12+pp]; }
    else if(tid<180){ int ii=tid-176; qnv[ii]=g_qn[(i0+ii)*NH+h]; mi[ii]=mask[i0+ii]; }
    else if(tid==180){ float xw=pweights[h]; s_pw=0.5f*log1pf(expf(xw)); }
    __syncthreads();

    float lv[3][4];
    const float invs = 0.17677669529663687f;
    #pragma unroll
    for(int jj=0;jj<3;jj++){
        int j=jj*256+tid;
        float sl[4]={0,0,0,0};
        const float* kt = g_kt + h*32*LL + j;
        #pragma unroll
        for(int c=0;c<32;c++){
            float kc=kt[c*LL];
            sl[0]+=qv[0][c]*kc; sl[1]+=qv[1][c]*kc; sl[2]+=qv[2][c]*kc; sl[3]+=qv[3][c]*kc;
        }
        float pd[4]={0,0,0,0};
        const float* kp = g_kpgt + h*12*LL + j;
        #pragma unroll
        for(int pp=0;pp<12;pp++){
            float kc=kp[pp*LL];
            pd[0]+=qp[0][pp]*kc; pd[1]+=qp[1][pp]*kc; pd[2]+=qp[2][pp]*kc; pd[3]+=qp[3][pp]*kc;
        }
        float knj=g_knt[h*LL+j], mj=mask[j];
        const float* pbp = g_pb + ((long)h*LL+i0)*LL + j;
        #pragma unroll
        for(int ii=0;ii<4;ii++){
            float lg = sl[ii]*invs + pbp[(long)ii*LL] - s_pw*(qnv[ii]+knj-2.f*pd[ii]);
            if (mi[ii]*mj==0.f) lg=-1e9f;
            lv[jj][ii]=lg;
        }
    }
    #pragma unroll
    for(int ii=0;ii<4;ii++){
        float m=fmaxf(fmaxf(lv[0][ii],lv[1][ii]),lv[2][ii]);
        #pragma unroll
        for(int o=16;o;o>>=1) m=fmaxf(m,__shfl_xor_sync(~0u,m,o));
        if((tid&31)==0) red[tid>>5][ii]=m;
    }
    __syncthreads();
    if(tid<4){ float m=red[0][tid]; for(int w=1;w<8;w++)m=fmaxf(m,red[w][tid]); bmax[tid]=m; }
    __syncthreads();
    float ev[3][4], sm[4]={0,0,0,0};
    #pragma unroll
    for(int jj=0;jj<3;jj++)
        #pragma unroll
        for(int ii=0;ii<4;ii++){ float e=__expf(lv[jj][ii]-bmax[ii]); ev[jj][ii]=e; sm[ii]+=e; }
    __syncthreads();
    #pragma unroll
    for(int ii=0;ii<4;ii++){
        float s=sm[ii];
        #pragma unroll
        for(int o=16;o;o>>=1) s+=__shfl_xor_sync(~0u,s,o);
        if((tid&31)==0) red[tid>>5][ii]=s;
    }
    __syncthreads();
    if(tid<4){ float s=0; for(int w=0;w<8;w++)s+=red[w][tid]; brcp[tid]=1.f/s; }
    __syncthreads();
    #pragma unroll
    for(int jj=0;jj<3;jj++){
        int j=jj*256+tid;
        #pragma unroll
        for(int ii=0;ii<4;ii++)
            attn[((long)h*LL+i0+ii)*LL+j]=ev[jj][ii]*brcp[ii];
    }
}

// ---- attn @ V (per-head, Nh<=32) ----
__global__ __launch_bounds__(256) void k_attn_apply(const float* __restrict__ attn,
                                                    const float* __restrict__ V,
                                                    float* __restrict__ out,
                                                    int Nh, int ldv, int ldo, int col0){
    int h=blockIdx.y, i0=blockIdx.x*16, tid=threadIdx.x;
    __shared__ float As[16][33], Vs[32][33];
    int n=tid&31, iw=tid>>5;
    float acc0=0.f, acc1=0.f;
    for(int j0=0;j0<LL;j0+=32){
        for(int l=tid;l<512;l+=256){
            int r=l>>5, jj=l&31;
            As[r][jj]=attn[((long)h*LL+i0+r)*LL+j0+jj];
        }
        for(int l=tid;l<1024;l+=256){
            int r=l>>5, nn=l&31;
            Vs[r][nn]=(nn<Nh)?V[(j0+r)*ldv+h*Nh+nn]:0.f;
        }
        __syncthreads();
        #pragma unroll
        for(int jj=0;jj<32;jj++){
            float vv=Vs[jj][n];
            acc0+=As[iw][jj]*vv; acc1+=As[iw+8][jj]*vv;
        }
        __syncthreads();
    }
    if(n<Nh){
        out[(i0+iw)*ldo+col0+h*Nh+n]=acc0;
        out[(i0+iw+8)*ldo+col0+h*Nh+n]=acc1;
    }
}

// ---- pair_out: out[i,h*4+d] = sum_j attn[h,i,j]*pv[i*768+j][h*4+d] ----
__global__ __launch_bounds__(256) void k_pair_out(const float* __restrict__ attn){
    int i=blockIdx.x, tid=threadIdx.x;
    int o=tid&31, jw=tid>>5, h=o>>2;
    float acc=0.f;
    for(int j=jw;j<LL;j+=8)
        acc += attn[((long)h*LL+i)*LL+j]*g_pv[((long)i*LL+j)*32+o];
    __shared__ float red[8][32];
    red[jw][o]=acc;
    __syncthreads();
    if(tid<32){
        float s=0; for(int w=0;w<8;w++)s+=red[w][tid];
        g_feat[i*FEAT+512+tid]=s;
    }
}

// ---- back to local frame + norms ----
__global__ __launch_bounds__(64) void k_local(const float* __restrict__ R,
                                              const float* __restrict__ t){
    int i=blockIdx.x, tid=threadIdx.x;  // tid = h*8+p
    __shared__ float Rl[9], tl[3];
    if(tid<9) Rl[tid]=R[i*9+tid];
    if(tid<3) tl[tid]=t[i*3+tid];
    __syncthreads();
    float gx=g_ptg[i*192+tid*3]  -tl[0];
    float gy=g_ptg[i*192+tid*3+1]-tl[1];
    float gz=g_ptg[i*192+tid*3+2]-tl[2];
    float lx=Rl[0]*gx+Rl[3]*gy+Rl[6]*gz;
    float ly=Rl[1]*gx+Rl[4]*gy+Rl[7]*gz;
    float lz=Rl[2]*gx+Rl[5]*gy+Rl[8]*gz;
    g_feat[i*FEAT+256+tid*3]  =lx;
    g_feat[i*FEAT+256+tid*3+1]=ly;
    g_feat[i*FEAT+256+tid*3+2]=lz;
    g_feat[i*FEAT+448+tid]=sqrtf(lx*lx+ly*ly+lz*lz+1e-8f);
}

extern "C" void kernel_launch(void* const* d_in, const int* in_sizes, int n_in,
                              void* d_out, int out_size){
    const float* s      =(const float*)d_in[0];
    const float* z      =(const float*)d_in[1];
    const float* R      =(const float*)d_in[2];
    const float* t      =(const float*)d_in[3];
    const float* mask   =(const float*)d_in[4];
    const float* ln_s_w =(const float*)d_in[5];
    const float* ln_s_b =(const float*)d_in[6];
    const float* ln_z_w =(const float*)d_in[7];
    const float* ln_z_b =(const float*)d_in[8];
    const float* Wq     =(const float*)d_in[9];
    const float* Wk     =(const float*)d_in[10];
    const float* Wv     =(const float*)d_in[11];
    const float* Wpb    =(const float*)d_in[12];
    const float* Wq_pts =(const float*)d_in[13];
    const float* Wk_pts =(const float*)d_in[14];
    const float* Wv_pts =(const float*)d_in[15];
    const float* pw     =(const float*)d_in[16];
    const float* Wpo    =(const float*)d_in[17];
    const float* W_out  =(const float*)d_in[18];
    const float* b_out  =(const float*)d_in[19];
    float* out  = (float*)d_out;
    float* attn = out + ATTN_OFF;

    float *p_sln,*p_q,*p_k,*p_v,*p_qpl,*p_kpl,*p_vpl,*p_vpg,*p_feat,*p_ptg;
    cudaGetSymbolAddress((void**)&p_sln, g_sln);
    cudaGetSymbolAddress((void**)&p_q,   g_q);
    cudaGetSymbolAddress((void**)&p_k,   g_k);
    cudaGetSymbolAddress((void**)&p_v,   g_v);
    cudaGetSymbolAddress((void**)&p_qpl, g_qpl);
    cudaGetSymbolAddress((void**)&p_kpl, g_kpl);
    cudaGetSymbolAddress((void**)&p_vpl, g_vpl);
    cudaGetSymbolAddress((void**)&p_vpg, g_vpg);
    cudaGetSymbolAddress((void**)&p_feat,g_feat);
    cudaGetSymbolAddress((void**)&p_ptg, g_ptg);

    k_ln_s<<<LL,256>>>(s, ln_s_w, ln_s_b);
    k_premix<<<1,64>>>(ln_z_w, ln_z_b, Wpb, Wpo);
    k_zpass<<<(LL*LL)/128,256>>>(z, ln_z_w, Wpb, Wpo);
    k_sgemm<<<dim3(4,12),256>>>(p_sln, Wq,     nullptr, nullptr, p_q,   LL,256,CS);
    k_sgemm<<<dim3(4,12),256>>>(p_sln, Wk,     nullptr, nullptr, p_k,   LL,256,CS);
    k_sgemm<<<dim3(4,12),256>>>(p_sln, Wv,     nullptr, nullptr, p_v,   LL,256,CS);
    k_sgemm<<<dim3(2,12),256>>>(p_sln, Wq_pts, nullptr, nullptr, p_qpl, LL, 96,CS);
    k_sgemm<<<dim3(2,12),256>>>(p_sln, Wk_pts, nullptr, nullptr, p_kpl, LL, 96,CS);
    k_sgemm<<<dim3(3,12),256>>>(p_sln, Wv_pts, nullptr, nullptr, p_vpl, LL,192,CS);
    k_transpose_k<<<dim3(8,24),256>>>();
    k_transform<<<LL,128>>>(R, t);
    k_logits_softmax<<<dim3(LL/4,NH),256>>>(mask, pw, attn);
    k_attn_apply<<<dim3(LL/16,NH),256>>>(attn, p_v,   p_feat, 32, 256, FEAT, 0);
    k_attn_apply<<<dim3(LL/16,NH),256>>>(attn, p_vpg, p_ptg,  24, 192, 192,  0);
    k_pair_out<<<LL,256>>>(attn);
    k_local<<<LL,64>>>(R, t);
    k_sgemm<<<dim3(4,12),256>>>(p_feat, W_out, b_out, mask, out, LL, 256, FEAT);
}

// round 6
// speedup vs baseline: 2.0401x; 2.0401x over previous
#include <cuda_runtime.h>
#include <math.h>

#define LL 768
#define CS 256
#define CZ 128
#define NH 8
#define FEAT 544
#define NPROJ 1152
#define ATTN_OFF (LL*CS)

// g_proj column offsets: Q=0, K=256, V=512, QPL=768, KPL=864, VPL=960
#define OFF_Q   0
#define OFF_K   256
#define OFF_V   512
#define OFF_QPL 768
#define OFF_KPL 864
#define OFF_VPL 960

__device__ float g_sln[LL*CS];
__device__ float g_Wcat[CS*NPROJ];
__device__ float g_proj[LL*NPROJ];
__device__ float g_kt[CS*LL];            // [c][j]
__device__ float g_qpg[LL*96];           // [i][h*12+pp]
__device__ float g_kpgt[96*LL];          // [(h*12+pp)][j]
__device__ float g_vpg[LL*192];          // [j][h*24+pp]
__device__ float g_qn[LL*NH];
__device__ float g_knt[NH*LL];
__device__ float g_pb[(long)NH*LL*LL];   // [h][i][j]
__device__ float g_pv[(long)LL*LL*32];   // [pair][h*4+d]
__device__ float g_feat[LL*FEAT];
__device__ float g_ptg[LL*192];
__device__ float g_T1[40];
__device__ float g_T0[40];
__device__ unsigned long long g_Wz[CZ*20];   // lnw-folded f32x2-packed z weights

__device__ __forceinline__ unsigned long long pk2(float lo, float hi){
    unsigned long long r; asm("mov.b64 %0,{%1,%2};":"=l"(r):"f"(lo),"f"(hi)); return r;
}
__device__ __forceinline__ void fma2(unsigned long long &d, unsigned long long a, unsigned long long b){
    asm("fma.rn.f32x2 %0, %1, %2, %0;" : "+l"(d) : "l"(a), "l"(b));
}
__device__ __forceinline__ float2 upk2(unsigned long long v){
    float2 r; asm("mov.b64 {%0,%1},%2;":"=f"(r.x),"=f"(r.y):"l"(v)); return r;
}

// ---- LN of s ----
__global__ __launch_bounds__(256) void k_ln_s(const float* __restrict__ s,
                                              const float* __restrict__ w,
                                              const float* __restrict__ b){
    int i = blockIdx.x, t = threadIdx.x;
    float x = s[i*CS + t];
    __shared__ float sh[8]; __shared__ float s_m, s_r;
    float v = x;
    #pragma unroll
    for (int o=16;o;o>>=1) v += __shfl_xor_sync(~0u,v,o);
    if ((t&31)==0) sh[t>>5]=v;
    __syncthreads();
    if (t==0){ float u=0; for(int kk=0;kk<8;kk++)u+=sh[kk]; s_m=u*(1.f/256.f); }
    __syncthreads();
    float d = x - s_m; v = d*d;
    #pragma unroll
    for (int o=16;o;o>>=1) v += __shfl_xor_sync(~0u,v,o);
    if ((t&31)==0) sh[t>>5]=v;
    __syncthreads();
    if (t==0){ float u=0; for(int kk=0;kk<8;kk++)u+=sh[kk]; s_r=rsqrtf(u*(1.f/256.f)+1e-5f); }
    __syncthreads();
    g_sln[i*CS+t] = d*s_r*w[t] + b[t];
}

// ---- premix: pack z-weights (lnw folded, f32x2) + T1/T0 fold constants ----
__global__ void k_premix(const float* __restrict__ lnw, const float* __restrict__ lnb,
                         const float* __restrict__ Wpb, const float* __restrict__ Wpo){
    int idx = blockIdx.x*256 + threadIdx.x;
    if (idx < 2560){
        int c = idx/20, np = idx%20, n = np*2;
        float w0 = lnw[c]*((n  <8)?Wpb[c*8+n  ]:Wpo[c*32+n-8]);
        float w1 = lnw[c]*((n+1<8)?Wpb[c*8+n+1]:Wpo[c*32+n-7]);
        g_Wz[idx] = pk2(w0,w1);
    } else if (idx < 2600){
        int n = idx-2560;
        float t1=0.f, t0=0.f;
        for(int c=0;c<CZ;c++){
            float wv = (n<8)?Wpb[c*8+n]:Wpo[c*32+n-8];
            t1 += lnw[c]*wv; t0 += lnb[c]*wv;
        }
        g_T1[n]=t1; g_T0[n]=t0;
    }
}

// ---- concat projection weights into [256][1152] ----
__global__ __launch_bounds__(256) void k_wcat(const float* __restrict__ Wq, const float* __restrict__ Wk,
                                              const float* __restrict__ Wv, const float* __restrict__ Wqp,
                                              const float* __restrict__ Wkp, const float* __restrict__ Wvp){
    int idx = blockIdx.x*256 + threadIdx.x;
    int k = idx/NPROJ, n = idx%NPROJ;
    float v;
    if      (n < 256)  v = Wq [k*256 + n];
    else if (n < 512)  v = Wk [k*256 + n-256];
    else if (n < 768)  v = Wv [k*256 + n-512];
    else if (n < 864)  v = Wqp[k*96  + n-768];
    else if (n < 960)  v = Wkp[k*96  + n-864];
    else               v = Wvp[k*192 + n-960];
    g_Wcat[idx] = v;
}

// ---- high-throughput SGEMM: C[M,N] = A[M,K] @ W[K,N] (+bias)(*mask)
//      requires M%64==0, N%64==0, K%16==0 ----
__global__ __launch_bounds__(256) void k_sgemm2(const float* __restrict__ A,
                                                const float* __restrict__ W,
                                                const float* __restrict__ bias,
                                                const float* __restrict__ msk,
                                                float* __restrict__ C,
                                                int M, int N, int K){
    __shared__ float As[16][68], Bs[16][68];
    int tid = threadIdx.x;
    int tx = tid&15, ty = tid>>4;
    const float* Ab = A + (long)(blockIdx.y*64)*K;
    const float* Wb = W + blockIdx.x*64;
    float acc[4][4];
    #pragma unroll
    for(int u=0;u<4;u++)
        #pragma unroll
        for(int w2=0;w2<4;w2++) acc[u][w2]=0.f;

    int ar = tid>>2, ak = (tid&3)*4;   // A stage: row ar, k sub
    int bk = tid>>4, bn = (tid&15)*4;  // B stage: k row bk, col sub
    float4 a4 = *(const float4*)&Ab[ar*K + ak];
    float4 b4 = *(const float4*)&Wb[(long)bk*N + bn];

    for(int k0=0;k0<K;k0+=16){
        As[ak+0][ar]=a4.x; As[ak+1][ar]=a4.y; As[ak+2][ar]=a4.z; As[ak+3][ar]=a4.w;
        *(float4*)&Bs[bk][bn]=b4;
        __syncthreads();
        if (k0+16 < K){
            a4 = *(const float4*)&Ab[ar*K + k0+16 + ak];
            b4 = *(const float4*)&Wb[(long)(k0+16+bk)*N + bn];
        }
        #pragma unroll
        for(int kk=0;kk<16;kk++){
            float4 av=*(const float4*)&As[kk][ty*4];
            float4 bv=*(const float4*)&Bs[kk][tx*4];
            float aa[4]={av.x,av.y,av.z,av.w};
            float bb[4]={bv.x,bv.y,bv.z,bv.w};
            #pragma unroll
            for(int u=0;u<4;u++)
                #pragma unroll
                for(int w2=0;w2<4;w2++) acc[u][w2] += aa[u]*bb[w2];
        }
        __syncthreads();
    }
    int gm0 = blockIdx.y*64 + ty*4, gn0 = blockIdx.x*64 + tx*4;
    #pragma unroll
    for(int u=0;u<4;u++){
        int gm = gm0+u;
        float mv = msk ? msk[gm] : 1.f;
        #pragma unroll
        for(int w2=0;w2<4;w2++){
            int gn = gn0+w2;
            float vv = acc[u][w2];
            if (bias) vv += bias[gn];
            C[(long)gm*N+gn] = vv*mv;
        }
    }
}

// ---- transpose k -> [c][j] ----
__global__ __launch_bounds__(256) void k_transpose_k(){
    __shared__ float tile[32][33];
    int c0=blockIdx.x*32, j0=blockIdx.y*32;
    int tx=threadIdx.x&31, ty=threadIdx.x>>5;
    for(int r=ty;r<32;r+=8) tile[r][tx]=g_proj[(j0+r)*NPROJ + OFF_K + c0+tx];
    __syncthreads();
    for(int r=ty;r<32;r+=8) g_kt[(c0+r)*LL+j0+tx]=tile[tx][r];
}

// ---- rigid transform of points + norms ----
__global__ __launch_bounds__(128) void k_transform(const float* __restrict__ R,
                                                   const float* __restrict__ t){
    int i=blockIdx.x, tid=threadIdx.x;
    __shared__ float Rl[9], tl[3];
    if(tid<9) Rl[tid]=R[i*9+tid];
    if(tid<3) tl[tid]=t[i*3+tid];
    __syncthreads();
    if (tid<32){
        const float* src = g_proj + i*NPROJ + OFF_QPL + tid*3;
        float p0=src[0], p1=src[1], p2=src[2];
        float gx=Rl[0]*p0+Rl[1]*p1+Rl[2]*p2+tl[0];
        float gy=Rl[3]*p0+Rl[4]*p1+Rl[5]*p2+tl[1];
        float gz=Rl[6]*p0+Rl[7]*p1+Rl[8]*p2+tl[2];
        g_qpg[i*96+tid*3]=gx; g_qpg[i*96+tid*3+1]=gy; g_qpg[i*96+tid*3+2]=gz;
        float sq=gx*gx+gy*gy+gz*gz;
        sq += __shfl_xor_sync(~0u,sq,1); sq += __shfl_xor_sync(~0u,sq,2);
        if((tid&3)==0) g_qn[i*NH+(tid>>2)]=sq;
    } else if (tid<64){
        int idx=tid-32;
        const float* src = g_proj + i*NPROJ + OFF_KPL + idx*3;
        float p0=src[0], p1=src[1], p2=src[2];
        float gx=Rl[0]*p0+Rl[1]*p1+Rl[2]*p2+tl[0];
        float gy=Rl[3]*p0+Rl[4]*p1+Rl[5]*p2+tl[1];
        float gz=Rl[6]*p0+Rl[7]*p1+Rl[8]*p2+tl[2];
        g_kpgt[(idx*3+0)*LL+i]=gx; g_kpgt[(idx*3+1)*LL+i]=gy; g_kpgt[(idx*3+2)*LL+i]=gz;
        float sq=gx*gx+gy*gy+gz*gz;
        sq += __shfl_xor_sync(~0u,sq,1); sq += __shfl_xor_sync(~0u,sq,2);
        if((idx&3)==0) g_knt[(idx>>2)*LL+i]=sq;
    } else {
        int idx=tid-64;
        const float* src = g_proj + i*NPROJ + OFF_VPL + idx*3;
        float p0=src[0], p1=src[1], p2=src[2];
        g_vpg[i*192+idx*3+0]=Rl[0]*p0+Rl[1]*p1+Rl[2]*p2+tl[0];
        g_vpg[i*192+idx*3+1]=Rl[3]*p0+Rl[4]*p1+Rl[5]*p2+tl[1];
        g_vpg[i*192+idx*3+2]=Rl[6]*p0+Rl[7]*p1+Rl[8]*p2+tl[2];
    }
}

// ---- z pass: LN folded, z read once -> pair_bias + pair_v ----
__global__ __launch_bounds__(256) void k_zpass(const float* __restrict__ z){
    __shared__ float Zs[16][129];
    __shared__ unsigned long long Ws[16][32];   // 20 used, padded for index math
    __shared__ float Os[128][41];
    __shared__ float s_mean[128], s_rstd[128], T1s[40], T0s[40];
    int tid=threadIdx.x;
    long pair0=(long)blockIdx.x*128;
    if(tid<40){ T1s[tid]=g_T1[tid]; T0s[tid]=g_T0[tid]; }

    int tx=tid&63, ty=tid>>6;
    unsigned long long acc2[2][5];
    #pragma unroll
    for(int m=0;m<2;m++)
        #pragma unroll
        for(int n=0;n<5;n++) acc2[m][n]=0ull;

    float sum0=0.f,sq0=0.f,sum1=0.f,sq1=0.f;
    int rA=tid>>2, kq=tid&3, rB=rA+64;

    float4 v4 = *(const float4*)&z[(pair0+rA)*CZ + kq*4];
    float4 w4 = *(const float4*)&z[(pair0+rB)*CZ + kq*4];

    for(int k0=0;k0<CZ;k0+=16){
        sum0 += v4.x+v4.y+v4.z+v4.w;
        sq0  += v4.x*v4.x+v4.y*v4.y+v4.z*v4.z+v4.w*v4.w;
        Zs[kq*4+0][rA]=v4.x; Zs[kq*4+1][rA]=v4.y; Zs[kq*4+2][rA]=v4.z; Zs[kq*4+3][rA]=v4.w;
        sum1 += w4.x+w4.y+w4.z+w4.w;
        sq1  += w4.x*w4.x+w4.y*w4.y+w4.z*w4.z+w4.w*w4.w;
        Zs[kq*4+0][rB]=w4.x; Zs[kq*4+1][rB]=w4.y; Zs[kq*4+2][rB]=w4.z; Zs[kq*4+3][rB]=w4.w;
        {   // stage 16x20 packed weights (no div/branch)
            int l0 = tid, l1 = tid+256;
            int kk0=l0>>5, np0=l0&31;
            if (np0<20) Ws[kk0][np0]=g_Wz[(k0+kk0)*20+np0];
            int kk1=l1>>5, np1=l1&31;
            if (np1<20) Ws[kk1][np1]=g_Wz[(k0+kk1)*20+np1];
        }
        __syncthreads();
        if (k0+16 < CZ){
            v4 = *(const float4*)&z[(pair0+rA)*CZ + k0+16 + kq*4];
            w4 = *(const float4*)&z[(pair0+rB)*CZ + k0+16 + kq*4];
        }
        #pragma unroll
        for(int kk=0;kk<16;kk++){
            float z0=Zs[kk][tx], z1=Zs[kk][tx+64];
            unsigned long long z20=pk2(z0,z0), z21=pk2(z1,z1);
            const unsigned long long* wrow = &Ws[kk][ty*5];
            #pragma unroll
            for(int nn=0;nn<5;nn++){
                unsigned long long wp=wrow[nn];
                fma2(acc2[0][nn],z20,wp);
                fma2(acc2[1][nn],z21,wp);
            }
        }
        __syncthreads();
    }
    sum0+=__shfl_xor_sync(~0u,sum0,1); sum0+=__shfl_xor_sync(~0u,sum0,2);
    sq0 +=__shfl_xor_sync(~0u,sq0,1);  sq0 +=__shfl_xor_sync(~0u,sq0,2);
    sum1+=__shfl_xor_sync(~0u,sum1,1); sum1+=__shfl_xor_sync(~0u,sum1,2);
    sq1 +=__shfl_xor_sync(~0u,sq1,1);  sq1 +=__shfl_xor_sync(~0u,sq1,2);
    if((tid&3)==0){
        int r=tid>>2;
        float m=sum0*(1.f/128.f);
        s_mean[r]=m; s_rstd[r]=rsqrtf(sq0*(1.f/128.f)-m*m+1e-5f);
        m=sum1*(1.f/128.f);
        s_mean[r+64]=m; s_rstd[r+64]=rsqrtf(sq1*(1.f/128.f)-m*m+1e-5f);
    }
    __syncthreads();
    #pragma unroll
    for(int m=0;m<2;m++){
        int r=tx+m*64;
        float rs=s_rstd[r], mn=s_mean[r];
        #pragma unroll
        for(int nn=0;nn<5;nn++){
            float2 a=upk2(acc2[m][nn]);
            int n=ty*10+nn*2;
            Os[r][n]  =rs*(a.x-mn*T1s[n])  +T0s[n];
            Os[r][n+1]=rs*(a.y-mn*T1s[n+1])+T0s[n+1];
        }
    }
    __syncthreads();
    for(int l=tid;l<1024;l+=256){
        int hh=l>>7, r=l&127;
        long p=pair0+r; int i=(int)(p/LL), j=(int)(p%LL);
        g_pb[((long)hh*LL+i)*LL+j]=Os[r][hh];
    }
    for(int l=tid;l<4096;l+=256){
        int r=l>>5, o=l&31;
        g_pv[(pair0+r)*32+o]=Os[r][8+o];
    }
}

// ---- fused logits + softmax -> attn (direct to d_out) ----
__global__ __launch_bounds__(256) void k_logits_softmax(const float* __restrict__ mask,
                                                        const float* __restrict__ pweights,
                                                        float* __restrict__ attn){
    int h=blockIdx.y, i0=blockIdx.x*4, tid=threadIdx.x;
    __shared__ float qv[4][32], qp[4][12], qnv[4], mi[4], red[8][4], bmax[4], brcp[4], s_pw;
    if(tid<128){ int ii=tid>>5, c=tid&31; qv[ii][c]=g_proj[(i0+ii)*NPROJ + OFF_Q + h*32+c]; }
    else if(tid<176){ int l=tid-128, ii=l/12, pp=l%12; qp[ii][pp]=g_qpg[(i0+ii)*96+h*12+pp]; }
    else if(tid<180){ int ii=tid-176; qnv[ii]=g_qn[(i0+ii)*NH+h]; mi[ii]=mask[i0+ii]; }
    else if(tid==180){ float xw=pweights[h]; s_pw=0.5f*log1pf(expf(xw)); }
    __syncthreads();

    float lv[3][4];
    const float invs = 0.17677669529663687f;
    #pragma unroll
    for(int jj=0;jj<3;jj++){
        int j=jj*256+tid;
        float sl[4]={0,0,0,0};
        const float* kt = g_kt + h*32*LL + j;
        #pragma unroll
        for(int c=0;c<32;c++){
            float kc=kt[c*LL];
            sl[0]+=qv[0][c]*kc; sl[1]+=qv[1][c]*kc; sl[2]+=qv[2][c]*kc; sl[3]+=qv[3][c]*kc;
        }
        float pd[4]={0,0,0,0};
        const float* kp = g_kpgt + h*12*LL + j;
        #pragma unroll
        for(int pp=0;pp<12;pp++){
            float kc=kp[pp*LL];
            pd[0]+=qp[0][pp]*kc; pd[1]+=qp[1][pp]*kc; pd[2]+=qp[2][pp]*kc; pd[3]+=qp[3][pp]*kc;
        }
        float knj=g_knt[h*LL+j], mj=mask[j];
        const float* pbp = g_pb + ((long)h*LL+i0)*LL + j;
        #pragma unroll
        for(int ii=0;ii<4;ii++){
            float lg = sl[ii]*invs + pbp[(long)ii*LL] - s_pw*(qnv[ii]+knj-2.f*pd[ii]);
            if (mi[ii]*mj==0.f) lg=-1e9f;
            lv[jj][ii]=lg;
        }
    }
    #pragma unroll
    for(int ii=0;ii<4;ii++){
        float m=fmaxf(fmaxf(lv[0][ii],lv[1][ii]),lv[2][ii]);
        #pragma unroll
        for(int o=16;o;o>>=1) m=fmaxf(m,__shfl_xor_sync(~0u,m,o));
        if((tid&31)==0) red[tid>>5][ii]=m;
    }
    __syncthreads();
    if(tid<4){ float m=red[0][tid]; for(int w=1;w<8;w++)m=fmaxf(m,red[w][tid]); bmax[tid]=m; }
    __syncthreads();
    float ev[3][4], sm[4]={0,0,0,0};
    #pragma unroll
    for(int jj=0;jj<3;jj++)
        #pragma unroll
        for(int ii=0;ii<4;ii++){ float e=__expf(lv[jj][ii]-bmax[ii]); ev[jj][ii]=e; sm[ii]+=e; }
    __syncthreads();
    #pragma unroll
    for(int ii=0;ii<4;ii++){
        float s=sm[ii];
        #pragma unroll
        for(int o=16;o;o>>=1) s+=__shfl_xor_sync(~0u,s,o);
        if((tid&31)==0) red[tid>>5][ii]=s;
    }
    __syncthreads();
    if(tid<4){ float s=0; for(int w=0;w<8;w++)s+=red[w][tid]; brcp[tid]=1.f/s; }
    __syncthreads();
    #pragma unroll
    for(int jj=0;jj<3;jj++){
        int j=jj*256+tid;
        #pragma unroll
        for(int ii=0;ii<4;ii++)
            attn[((long)h*LL+i0+ii)*LL+j]=ev[jj][ii]*brcp[ii];
    }
}

// ---- attn @ V (per-head, Nh<=32) ----
__global__ __launch_bounds__(256) void k_attn_apply(const float* __restrict__ attn,
                                                    const float* __restrict__ V,
                                                    float* __restrict__ out,
                                                    int Nh, int ldv, int ldo, int col0){
    int h=blockIdx.y, i0=blockIdx.x*16, tid=threadIdx.x;
    __shared__ float As[16][33], Vs[32][33];
    int n=tid&31, iw=tid>>5;
    float acc0=0.f, acc1=0.f;
    for(int j0=0;j0<LL;j0+=32){
        for(int l=tid;l<512;l+=256){
            int r=l>>5, jj=l&31;
            As[r][jj]=attn[((long)h*LL+i0+r)*LL+j0+jj];
        }
        for(int l=tid;l<1024;l+=256){
            int r=l>>5, nn=l&31;
            Vs[r][nn]=(nn<Nh)?V[(long)(j0+r)*ldv+h*Nh+nn]:0.f;
        }
        __syncthreads();
        #pragma unroll
        for(int jj=0;jj<32;jj++){
            float vv=Vs[jj][n];
            acc0+=As[iw][jj]*vv; acc1+=As[iw+8][jj]*vv;
        }
        __syncthreads();
    }
    if(n<Nh){
        out[(long)(i0+iw)*ldo+col0+h*Nh+n]=acc0;
        out[(long)(i0+iw+8)*ldo+col0+h*Nh+n]=acc1;
    }
}

// ---- pair_out: feat[i,512+h*4+d] = sum_j attn[h,i,j]*pv[i*768+j][h*4+d] ----
__global__ __launch_bounds__(256) void k_pair_out(const float* __restrict__ attn){
    int i=blockIdx.x, tid=threadIdx.x;
    int o=tid&31, jw=tid>>5, h=o>>2;
    float acc=0.f;
    for(int j=jw;j<LL;j+=8)
        acc += attn[((long)h*LL+i)*LL+j]*g_pv[((long)i*LL+j)*32+o];
    __shared__ float red[8][32];
    red[jw][o]=acc;
    __syncthreads();
    if(tid<32){
        float s=0; for(int w=0;w<8;w++)s+=red[w][tid];
        g_feat[i*FEAT+512+tid]=s;
    }
}

// ---- back to local frame + norms ----
__global__ __launch_bounds__(64) void k_local(const float* __restrict__ R,
                                              const float* __restrict__ t){
    int i=blockIdx.x, tid=threadIdx.x;
    __shared__ float Rl[9], tl[3];
    if(tid<9) Rl[tid]=R[i*9+tid];
    if(tid<3) tl[tid]=t[i*3+tid];
    __syncthreads();
    float gx=g_ptg[i*192+tid*3]  -tl[0];
    float gy=g_ptg[i*192+tid*3+1]-tl[1];
    float gz=g_ptg[i*192+tid*3+2]-tl[2];
    float lx=Rl[0]*gx+Rl[3]*gy+Rl[6]*gz;
    float ly=Rl[1]*gx+Rl[4]*gy+Rl[7]*gz;
    float lz=Rl[2]*gx+Rl[5]*gy+Rl[8]*gz;
    g_feat[i*FEAT+256+tid*3]  =lx;
    g_feat[i*FEAT+256+tid*3+1]=ly;
    g_feat[i*FEAT+256+tid*3+2]=lz;
    g_feat[i*FEAT+448+tid]=sqrtf(lx*lx+ly*ly+lz*lz+1e-8f);
}

extern "C" void kernel_launch(void* const* d_in, const int* in_sizes, int n_in,
                              void* d_out, int out_size){
    const float* s      =(const float*)d_in[0];
    const float* z      =(const float*)d_in[1];
    const float* R      =(const float*)d_in[2];
    const float* t      =(const float*)d_in[3];
    const float* mask   =(const float*)d_in[4];
    const float* ln_s_w =(const float*)d_in[5];
    const float* ln_s_b =(const float*)d_in[6];
    const float* ln_z_w =(const float*)d_in[7];
    const float* ln_z_b =(const float*)d_in[8];
    const float* Wq     =(const float*)d_in[9];
    const float* Wk     =(const float*)d_in[10];
    const float* Wv     =(const float*)d_in[11];
    const float* Wpb    =(const float*)d_in[12];
    const float* Wq_pts =(const float*)d_in[13];
    const float* Wk_pts =(const float*)d_in[14];
    const float* Wv_pts =(const float*)d_in[15];
    const float* pw     =(const float*)d_in[16];
    const float* Wpo    =(const float*)d_in[17];
    const float* W_out  =(const float*)d_in[18];
    const float* b_out  =(const float*)d_in[19];
    float* out  = (float*)d_out;
    float* attn = out + ATTN_OFF;

    float *p_sln,*p_wcat,*p_proj,*p_vpg,*p_feat,*p_ptg;
    cudaGetSymbolAddress((void**)&p_sln,  g_sln);
    cudaGetSymbolAddress((void**)&p_wcat, g_Wcat);
    cudaGetSymbolAddress((void**)&p_proj, g_proj);
    cudaGetSymbolAddress((void**)&p_vpg,  g_vpg);
    cudaGetSymbolAddress((void**)&p_feat, g_feat);
    cudaGetSymbolAddress((void**)&p_ptg,  g_ptg);

    k_ln_s<<<LL,256>>>(s, ln_s_w, ln_s_b);
    k_premix<<<11,256>>>(ln_z_w, ln_z_b, Wpb, Wpo);
    k_wcat<<<(CS*NPROJ)/256,256>>>(Wq, Wk, Wv, Wq_pts, Wk_pts, Wv_pts);
    k_zpass<<<(LL*LL)/128,256>>>(z);
    k_sgemm2<<<dim3(NPROJ/64, LL/64),256>>>(p_sln, p_wcat, nullptr, nullptr, p_proj, LL, NPROJ, CS);
    k_transpose_k<<<dim3(8,24),256>>>();
    k_transform<<<LL,128>>>(R, t);
    k_logits_softmax<<<dim3(LL/4,NH),256>>>(mask, pw, attn);
    k_attn_apply<<<dim3(LL/16,NH),256>>>(attn, p_proj + OFF_V, p_feat, 32, NPROJ, FEAT, 0);
    k_attn_apply<<<dim3(LL/16,NH),256>>>(attn, p_vpg,          p_ptg,  24, 192,   192,  0);
    k_pair_out<<<LL,256>>>(attn);
    k_local<<<LL,64>>>(R, t);
    k_sgemm2<<<dim3(CS/64, LL/64),256>>>(p_feat, W_out, b_out, mask, out, LL, CS, FEAT);
}

// round 7
// speedup vs baseline: 2.1200x; 1.0391x over previous
#include <cuda_runtime.h>
#include <math.h>

#define LL 768
#define CS 256
#define CZ 128
#define NH 8
#define FEAT 544
#define NPROJ 1152
#define ATTN_OFF (LL*CS)

#define OFF_Q   0
#define OFF_K   256
#define OFF_V   512
#define OFF_QPL 768
#define OFF_KPL 864
#define OFF_VPL 960

__device__ float g_sln[LL*CS];
__device__ float g_Wcat[CS*NPROJ];
__device__ float g_proj[LL*NPROJ];
__device__ float g_kt[CS*LL];            // [c][j]
__device__ float g_qpg[LL*96];           // [i][h*12+pp]
__device__ float g_kpgt[96*LL];          // [(h*12+pp)][j]
__device__ float g_vpg[LL*192];          // [j][h*24+pp]
__device__ float g_qn[LL*NH];
__device__ float g_knt[NH*LL];
__device__ float g_pb[(long)NH*LL*LL];   // [h][i][j]
__device__ float g_pv[(long)LL*LL*32];   // [pair][h*4+d]
__device__ float g_feat[LL*FEAT];
__device__ float g_ptg[LL*192];
__device__ float g_T1[40];
__device__ float g_T0[40];
__device__ unsigned long long g_Wz[CZ*20];   // lnw-folded f32x2-packed z weights

__device__ __forceinline__ unsigned long long pk2(float lo, float hi){
    unsigned long long r; asm("mov.b64 %0,{%1,%2};":"=l"(r):"f"(lo),"f"(hi)); return r;
}
__device__ __forceinline__ void fma2(unsigned long long &d, unsigned long long a, unsigned long long b){
    asm("fma.rn.f32x2 %0, %1, %2, %0;" : "+l"(d) : "l"(a), "l"(b));
}
__device__ __forceinline__ float2 upk2(unsigned long long v){
    float2 r; asm("mov.b64 {%0,%1},%2;":"=f"(r.x),"=f"(r.y):"l"(v)); return r;
}

// ---- LN of s ----
__global__ __launch_bounds__(256) void k_ln_s(const float* __restrict__ s,
                                              const float* __restrict__ w,
                                              const float* __restrict__ b){
    int i = blockIdx.x, t = threadIdx.x;
    float x = s[i*CS + t];
    __shared__ float sh[8]; __shared__ float s_m, s_r;
    float v = x;
    #pragma unroll
    for (int o=16;o;o>>=1) v += __shfl_xor_sync(~0u,v,o);
    if ((t&31)==0) sh[t>>5]=v;
    __syncthreads();
    if (t==0){ float u=0; for(int kk=0;kk<8;kk++)u+=sh[kk]; s_m=u*(1.f/256.f); }
    __syncthreads();
    float d = x - s_m; v = d*d;
    #pragma unroll
    for (int o=16;o;o>>=1) v += __shfl_xor_sync(~0u,v,o);
    if ((t&31)==0) sh[t>>5]=v;
    __syncthreads();
    if (t==0){ float u=0; for(int kk=0;kk<8;kk++)u+=sh[kk]; s_r=rsqrtf(u*(1.f/256.f)+1e-5f); }
    __syncthreads();
    g_sln[i*CS+t] = d*s_r*w[t] + b[t];
}

// ---- premix: pack z-weights (lnw folded, f32x2) + T1/T0 fold constants ----
__global__ void k_premix(const float* __restrict__ lnw, const float* __restrict__ lnb,
                         const float* __restrict__ Wpb, const float* __restrict__ Wpo){
    int idx = blockIdx.x*256 + threadIdx.x;
    if (idx < 2560){
        int c = idx/20, np = idx%20, n = np*2;
        float w0 = lnw[c]*((n  <8)?Wpb[c*8+n  ]:Wpo[c*32+n-8]);
        float w1 = lnw[c]*((n+1<8)?Wpb[c*8+n+1]:Wpo[c*32+n-7]);
        g_Wz[idx] = pk2(w0,w1);
    } else if (idx < 2600){
        int n = idx-2560;
        float t1=0.f, t0=0.f;
        for(int c=0;c<CZ;c++){
            float wv = (n<8)?Wpb[c*8+n]:Wpo[c*32+n-8];
            t1 += lnw[c]*wv; t0 += lnb[c]*wv;
        }
        g_T1[n]=t1; g_T0[n]=t0;
    }
}

// ---- concat projection weights into [256][1152] ----
__global__ __launch_bounds__(256) void k_wcat(const float* __restrict__ Wq, const float* __restrict__ Wk,
                                              const float* __restrict__ Wv, const float* __restrict__ Wqp,
                                              const float* __restrict__ Wkp, const float* __restrict__ Wvp){
    int idx = blockIdx.x*256 + threadIdx.x;
    int k = idx/NPROJ, n = idx%NPROJ;
    float v;
    if      (n < 256)  v = Wq [k*256 + n];
    else if (n < 512)  v = Wk [k*256 + n-256];
    else if (n < 768)  v = Wv [k*256 + n-512];
    else if (n < 864)  v = Wqp[k*96  + n-768];
    else if (n < 960)  v = Wkp[k*96  + n-864];
    else               v = Wvp[k*192 + n-960];
    g_Wcat[idx] = v;
}

// ---- high-throughput SGEMM: C[M,N] = A[M,K] @ W[K,N] (+bias)(*mask)
//      requires M%64==0, N%64==0, K%16==0 ----
__global__ __launch_bounds__(256) void k_sgemm2(const float* __restrict__ A,
                                                const float* __restrict__ W,
                                                const float* __restrict__ bias,
                                                const float* __restrict__ msk,
                                                float* __restrict__ C,
                                                int M, int N, int K){
    __shared__ float As[16][68], Bs[16][68];
    int tid = threadIdx.x;
    int tx = tid&15, ty = tid>>4;
    const float* Ab = A + (long)(blockIdx.y*64)*K;
    const float* Wb = W + blockIdx.x*64;
    float acc[4][4];
    #pragma unroll
    for(int u=0;u<4;u++)
        #pragma unroll
        for(int w2=0;w2<4;w2++) acc[u][w2]=0.f;

    int ar = tid>>2, ak = (tid&3)*4;
    int bk = tid>>4, bn = (tid&15)*4;
    float4 a4 = *(const float4*)&Ab[ar*K + ak];
    float4 b4 = *(const float4*)&Wb[(long)bk*N + bn];

    for(int k0=0;k0<K;k0+=16){
        As[ak+0][ar]=a4.x; As[ak+1][ar]=a4.y; As[ak+2][ar]=a4.z; As[ak+3][ar]=a4.w;
        *(float4*)&Bs[bk][bn]=b4;
        __syncthreads();
        if (k0+16 < K){
            a4 = *(const float4*)&Ab[ar*K + k0+16 + ak];
            b4 = *(const float4*)&Wb[(long)(k0+16+bk)*N + bn];
        }
        #pragma unroll
        for(int kk=0;kk<16;kk++){
            float4 av=*(const float4*)&As[kk][ty*4];
            float4 bv=*(const float4*)&Bs[kk][tx*4];
            float aa[4]={av.x,av.y,av.z,av.w};
            float bb[4]={bv.x,bv.y,bv.z,bv.w};
            #pragma unroll
            for(int u=0;u<4;u++)
                #pragma unroll
                for(int w2=0;w2<4;w2++) acc[u][w2] += aa[u]*bb[w2];
        }
        __syncthreads();
    }
    int gm0 = blockIdx.y*64 + ty*4, gn0 = blockIdx.x*64 + tx*4;
    #pragma unroll
    for(int u=0;u<4;u++){
        int gm = gm0+u;
        float mv = msk ? msk[gm] : 1.f;
        #pragma unroll
        for(int w2=0;w2<4;w2++){
            int gn = gn0+w2;
            float vv = acc[u][w2];
            if (bias) vv += bias[gn];
            C[(long)gm*N+gn] = vv*mv;
        }
    }
}

// ---- transpose k -> [c][j] ----
__global__ __launch_bounds__(256) void k_transpose_k(){
    __shared__ float tile[32][33];
    int c0=blockIdx.x*32, j0=blockIdx.y*32;
    int tx=threadIdx.x&31, ty=threadIdx.x>>5;
    for(int r=ty;r<32;r+=8) tile[r][tx]=g_proj[(j0+r)*NPROJ + OFF_K + c0+tx];
    __syncthreads();
    for(int r=ty;r<32;r+=8) g_kt[(c0+r)*LL+j0+tx]=tile[tx][r];
}

// ---- rigid transform of points + norms ----
__global__ __launch_bounds__(128) void k_transform(const float* __restrict__ R,
                                                   const float* __restrict__ t){
    int i=blockIdx.x, tid=threadIdx.x;
    __shared__ float Rl[9], tl[3];
    if(tid<9) Rl[tid]=R[i*9+tid];
    if(tid<3) tl[tid]=t[i*3+tid];
    __syncthreads();
    if (tid<32){
        const float* src = g_proj + i*NPROJ + OFF_QPL + tid*3;
        float p0=src[0], p1=src[1], p2=src[2];
        float gx=Rl[0]*p0+Rl[1]*p1+Rl[2]*p2+tl[0];
        float gy=Rl[3]*p0+Rl[4]*p1+Rl[5]*p2+tl[1];
        float gz=Rl[6]*p0+Rl[7]*p1+Rl[8]*p2+tl[2];
        g_qpg[i*96+tid*3]=gx; g_qpg[i*96+tid*3+1]=gy; g_qpg[i*96+tid*3+2]=gz;
        float sq=gx*gx+gy*gy+gz*gz;
        sq += __shfl_xor_sync(~0u,sq,1); sq += __shfl_xor_sync(~0u,sq,2);
        if((tid&3)==0) g_qn[i*NH+(tid>>2)]=sq;
    } else if (tid<64){
        int idx=tid-32;
        const float* src = g_proj + i*NPROJ + OFF_KPL + idx*3;
        float p0=src[0], p1=src[1], p2=src[2];
        float gx=Rl[0]*p0+Rl[1]*p1+Rl[2]*p2+tl[0];
        float gy=Rl[3]*p0+Rl[4]*p1+Rl[5]*p2+tl[1];
        float gz=Rl[6]*p0+Rl[7]*p1+Rl[8]*p2+tl[2];
        g_kpgt[(idx*3+0)*LL+i]=gx; g_kpgt[(idx*3+1)*LL+i]=gy; g_kpgt[(idx*3+2)*LL+i]=gz;
        float sq=gx*gx+gy*gy+gz*gz;
        sq += __shfl_xor_sync(~0u,sq,1); sq += __shfl_xor_sync(~0u,sq,2);
        if((idx&3)==0) g_knt[(idx>>2)*LL+i]=sq;
    } else {
        int idx=tid-64;
        const float* src = g_proj + i*NPROJ + OFF_VPL + idx*3;
        float p0=src[0], p1=src[1], p2=src[2];
        g_vpg[i*192+idx*3+0]=Rl[0]*p0+Rl[1]*p1+Rl[2]*p2+tl[0];
        g_vpg[i*192+idx*3+1]=Rl[3]*p0+Rl[4]*p1+Rl[5]*p2+tl[1];
        g_vpg[i*192+idx*3+2]=Rl[6]*p0+Rl[7]*p1+Rl[8]*p2+tl[2];
    }
}

// ---- z pass: LN folded, z read once -> pair_bias + pair_v
//      M-tile 256, 4 consecutive rows per thread, Zs transposed + XOR swizzle ----
__global__ __launch_bounds__(256) void k_zpass(const float* __restrict__ z){
    __shared__ __align__(16) float U[256*41];       // union: Zs[16][264] then Os[256][41]
    __shared__ unsigned long long Ws[16][20];
    __shared__ float s_mean[256], s_rstd[256], T1s[40], T0s[40];
    float* Zs = U;
    float (*Os)[41] = (float(*)[41])U;
    int tid=threadIdx.x;
    long pair0=(long)blockIdx.x*256;
    if(tid<40){ T1s[tid]=g_T1[tid]; T0s[tid]=g_T0[tid]; }

    int rbase = (tid&63)*4;
    int ty = tid>>6;
    unsigned long long acc2[4][5];
    #pragma unroll
    for(int m=0;m<4;m++)
        #pragma unroll
        for(int n=0;n<5;n++) acc2[m][n]=0ull;

    int rq = tid>>2, kq = tid&3;
    float sums[4]={0,0,0,0}, sqs[4]={0,0,0,0};
    float4 pf[4];
    #pragma unroll
    for(int i=0;i<4;i++) pf[i] = *(const float4*)&z[(pair0+rq+64*i)*CZ + kq*4];

    for(int k0=0;k0<CZ;k0+=16){
        #pragma unroll
        for(int i=0;i<4;i++){
            float4 v=pf[i];
            sums[i]+=v.x+v.y+v.z+v.w;
            sqs[i]+=v.x*v.x+v.y*v.y+v.z*v.z+v.w*v.w;
            int row=rq+64*i, kkb=kq*4;
            Zs[(kkb+0)*264 + (row ^ (((kkb+0)&7)<<2))]=v.x;
            Zs[(kkb+1)*264 + (row ^ (((kkb+1)&7)<<2))]=v.y;
            Zs[(kkb+2)*264 + (row ^ (((kkb+2)&7)<<2))]=v.z;
            Zs[(kkb+3)*264 + (row ^ (((kkb+3)&7)<<2))]=v.w;
        }
        {
            int l0=tid, l1=tid+256;
            int kk0=l0>>5, np0=l0&31; if(np0<20) Ws[kk0][np0]=g_Wz[(k0+kk0)*20+np0];
            int kk1=l1>>5, np1=l1&31; if(np1<20) Ws[kk1][np1]=g_Wz[(k0+kk1)*20+np1];
        }
        __syncthreads();
        if(k0+16<CZ){
            #pragma unroll
            for(int i=0;i<4;i++) pf[i]=*(const float4*)&z[(pair0+rq+64*i)*CZ + k0+16 + kq*4];
        }
        #pragma unroll
        for(int kk=0;kk<16;kk++){
            float4 z4 = *(const float4*)&Zs[kk*264 + (rbase ^ ((kk&7)<<2))];
            unsigned long long zp0=pk2(z4.x,z4.x), zp1=pk2(z4.y,z4.y);
            unsigned long long zp2=pk2(z4.z,z4.z), zp3=pk2(z4.w,z4.w);
            const unsigned long long* wrow=&Ws[kk][ty*5];
            #pragma unroll
            for(int nn=0;nn<5;nn++){
                unsigned long long wp=wrow[nn];
                fma2(acc2[0][nn],zp0,wp);
                fma2(acc2[1][nn],zp1,wp);
                fma2(acc2[2][nn],zp2,wp);
                fma2(acc2[3][nn],zp3,wp);
            }
        }
        __syncthreads();
    }
    #pragma unroll
    for(int i=0;i<4;i++){
        sums[i]+=__shfl_xor_sync(~0u,sums[i],1); sums[i]+=__shfl_xor_sync(~0u,sums[i],2);
        sqs[i] +=__shfl_xor_sync(~0u,sqs[i],1);  sqs[i] +=__shfl_xor_sync(~0u,sqs[i],2);
    }
    if(kq==0){
        #pragma unroll
        for(int i=0;i<4;i++){
            float m=sums[i]*(1.f/128.f);
            s_mean[rq+64*i]=m;
            s_rstd[rq+64*i]=rsqrtf(sqs[i]*(1.f/128.f)-m*m+1e-5f);
        }
    }
    __syncthreads();
    #pragma unroll
    for(int rr=0;rr<4;rr++){
        int r=rbase+rr;
        float rs=s_rstd[r], mn=s_mean[r];
        #pragma unroll
        for(int nn=0;nn<5;nn++){
            float2 a=upk2(acc2[rr][nn]);
            int n=ty*10+nn*2;
            Os[r][n]  =rs*(a.x-mn*T1s[n])  +T0s[n];
            Os[r][n+1]=rs*(a.y-mn*T1s[n+1])+T0s[n+1];
        }
    }
    __syncthreads();
    for(int l=tid;l<2048;l+=256){
        int hh=l>>8, r=l&255;
        long p=pair0+r; int i=(int)(p/LL), j=(int)(p%LL);
        g_pb[((long)hh*LL+i)*LL+j]=Os[r][hh];
    }
    for(int l=tid;l<8192;l+=256){
        int r=l>>5, o=l&31;
        g_pv[(pair0+r)*32+o]=Os[r][8+o];
    }
}

// ---- fused logits + softmax -> attn (direct to d_out) ----
__global__ __launch_bounds__(256) void k_logits_softmax(const float* __restrict__ mask,
                                                        const float* __restrict__ pweights,
                                                        float* __restrict__ attn){
    int h=blockIdx.y, i0=blockIdx.x*4, tid=threadIdx.x;
    __shared__ float qv[4][32], qp[4][12], qnv[4], mi[4], red[8][4], bmax[4], brcp[4], s_pw;
    if(tid<128){ int ii=tid>>5, c=tid&31; qv[ii][c]=g_proj[(i0+ii)*NPROJ + OFF_Q + h*32+c]; }
    else if(tid<176){ int l=tid-128, ii=l/12, pp=l%12; qp[ii][pp]=g_qpg[(i0+ii)*96+h*12+pp]; }
    else if(tid<180){ int ii=tid-176; qnv[ii]=g_qn[(i0+ii)*NH+h]; mi[ii]=mask[i0+ii]; }
    else if(tid==180){ float xw=pweights[h]; s_pw=0.5f*log1pf(expf(xw)); }
    __syncthreads();

    float lv[3][4];
    const float invs = 0.17677669529663687f;
    #pragma unroll
    for(int jj=0;jj<3;jj++){
        int j=jj*256+tid;
        float sl[4]={0,0,0,0};
        const float* kt = g_kt + h*32*LL + j;
        #pragma unroll
        for(int c=0;c<32;c++){
            float kc=kt[c*LL];
            sl[0]+=qv[0][c]*kc; sl[1]+=qv[1][c]*kc; sl[2]+=qv[2][c]*kc; sl[3]+=qv[3][c]*kc;
        }
        float pd[4]={0,0,0,0};
        const float* kp = g_kpgt + h*12*LL + j;
        #pragma unroll
        for(int pp=0;pp<12;pp++){
            float kc=kp[pp*LL];
            pd[0]+=qp[0][pp]*kc; pd[1]+=qp[1][pp]*kc; pd[2]+=qp[2][pp]*kc; pd[3]+=qp[3][pp]*kc;
        }
        float knj=g_knt[h*LL+j], mj=mask[j];
        const float* pbp = g_pb + ((long)h*LL+i0)*LL + j;
        #pragma unroll
        for(int ii=0;ii<4;ii++){
            float lg = sl[ii]*invs + pbp[(long)ii*LL] - s_pw*(qnv[ii]+knj-2.f*pd[ii]);
            if (mi[ii]*mj==0.f) lg=-1e9f;
            lv[jj][ii]=lg;
        }
    }
    #pragma unroll
    for(int ii=0;ii<4;ii++){
        float m=fmaxf(fmaxf(lv[0][ii],lv[1][ii]),lv[2][ii]);
        #pragma unroll
        for(int o=16;o;o>>=1) m=fmaxf(m,__shfl_xor_sync(~0u,m,o));
        if((tid&31)==0) red[tid>>5][ii]=m;
    }
    __syncthreads();
    if(tid<4){ float m=red[0][tid]; for(int w=1;w<8;w++)m=fmaxf(m,red[w][tid]); bmax[tid]=m; }
    __syncthreads();
    float ev[3][4], sm[4]={0,0,0,0};
    #pragma unroll
    for(int jj=0;jj<3;jj++)
        #pragma unroll
        for(int ii=0;ii<4;ii++){ float e=__expf(lv[jj][ii]-bmax[ii]); ev[jj][ii]=e; sm[ii]+=e; }
    __syncthreads();
    #pragma unroll
    for(int ii=0;ii<4;ii++){
        float s=sm[ii];
        #pragma unroll
        for(int o=16;o;o>>=1) s+=__shfl_xor_sync(~0u,s,o);
        if((tid&31)==0) red[tid>>5][ii]=s;
    }
    __syncthreads();
    if(tid<4){ float s=0; for(int w=0;w<8;w++)s+=red[w][tid]; brcp[tid]=1.f/s; }
    __syncthreads();
    #pragma unroll
    for(int jj=0;jj<3;jj++){
        int j=jj*256+tid;
        #pragma unroll
        for(int ii=0;ii<4;ii++)
            attn[((long)h*LL+i0+ii)*LL+j]=ev[jj][ii]*brcp[ii];
    }
}

// ---- attn @ V (per-head, Nh<=32) ----
__global__ __launch_bounds__(256) void k_attn_apply(const float* __restrict__ attn,
                                                    const float* __restrict__ V,
                                                    float* __restrict__ out,
                                                    int Nh, int ldv, int ldo, int col0){
    int h=blockIdx.y, i0=blockIdx.x*16, tid=threadIdx.x;
    __shared__ float As[16][33], Vs[32][33];
    int n=tid&31, iw=tid>>5;
    float acc0=0.f, acc1=0.f;
    for(int j0=0;j0<LL;j0+=32){
        for(int l=tid;l<512;l+=256){
            int r=l>>5, jj=l&31;
            As[r][jj]=attn[((long)h*LL+i0+r)*LL+j0+jj];
        }
        for(int l=tid;l<1024;l+=256){
            int r=l>>5, nn=l&31;
            Vs[r][nn]=(nn<Nh)?V[(long)(j0+r)*ldv+h*Nh+nn]:0.f;
        }
        __syncthreads();
        #pragma unroll
        for(int jj=0;jj<32;jj++){
            float vv=Vs[jj][n];
            acc0+=As[iw][jj]*vv; acc1+=As[iw+8][jj]*vv;
        }
        __syncthreads();
    }
    if(n<Nh){
        out[(long)(i0+iw)*ldo+col0+h*Nh+n]=acc0;
        out[(long)(i0+iw+8)*ldo+col0+h*Nh+n]=acc1;
    }
}

// ---- pair_out ----
__global__ __launch_bounds__(256) void k_pair_out(const float* __restrict__ attn){
    int i=blockIdx.x, tid=threadIdx.x;
    int o=tid&31, jw=tid>>5, h=o>>2;
    float acc=0.f;
    for(int j=jw;j<LL;j+=8)
        acc += attn[((long)h*LL+i)*LL+j]*g_pv[((long)i*LL+j)*32+o];
    __shared__ float red[8][32];
    red[jw][o]=acc;
    __syncthreads();
    if(tid<32){
        float s=0; for(int w=0;w<8;w++)s+=red[w][tid];
        g_feat[i*FEAT+512+tid]=s;
    }
}

// ---- back to local frame + norms ----
__global__ __launch_bounds__(64) void k_local(const float* __restrict__ R,
                                              const float* __restrict__ t){
    int i=blockIdx.x, tid=threadIdx.x;
    __shared__ float Rl[9], tl[3];
    if(tid<9) Rl[tid]=R[i*9+tid];
    if(tid<3) tl[tid]=t[i*3+tid];
    __syncthreads();
    float gx=g_ptg[i*192+tid*3]  -tl[0];
    float gy=g_ptg[i*192+tid*3+1]-tl[1];
    float gz=g_ptg[i*192+tid*3+2]-tl[2];
    float lx=Rl[0]*gx+Rl[3]*gy+Rl[6]*gz;
    float ly=Rl[1]*gx+Rl[4]*gy+Rl[7]*gz;
    float lz=Rl[2]*gx+Rl[5]*gy+Rl[8]*gz;
    g_feat[i*FEAT+256+tid*3]  =lx;
    g_feat[i*FEAT+256+tid*3+1]=ly;
    g_feat[i*FEAT+256+tid*3+2]=lz;
    g_feat[i*FEAT+448+tid]=sqrtf(lx*lx+ly*ly+lz*lz+1e-8f);
}

extern "C" void kernel_launch(void* const* d_in, const int* in_sizes, int n_in,
                              void* d_out, int out_size){
    const float* s      =(const float*)d_in[0];
    const float* z      =(const float*)d_in[1];
    const float* R      =(const float*)d_in[2];
    const float* t      =(const float*)d_in[3];
    const float* mask   =(const float*)d_in[4];
    const float* ln_s_w =(const float*)d_in[5];
    const float* ln_s_b =(const float*)d_in[6];
    const float* ln_z_w =(const float*)d_in[7];
    const float* ln_z_b =(const float*)d_in[8];
    const float* Wq     =(const float*)d_in[9];
    const float* Wk     =(const float*)d_in[10];
    const float* Wv     =(const float*)d_in[11];
    const float* Wpb    =(const float*)d_in[12];
    const float* Wq_pts =(const float*)d_in[13];
    const float* Wk_pts =(const float*)d_in[14];
    const float* Wv_pts =(const float*)d_in[15];
    const float* pw     =(const float*)d_in[16];
    const float* Wpo    =(const float*)d_in[17];
    const float* W_out  =(const float*)d_in[18];
    const float* b_out  =(const float*)d_in[19];
    float* out  = (float*)d_out;
    float* attn = out + ATTN_OFF;

    float *p_sln,*p_wcat,*p_proj,*p_vpg,*p_feat,*p_ptg;
    cudaGetSymbolAddress((void**)&p_sln,  g_sln);
    cudaGetSymbolAddress((void**)&p_wcat, g_Wcat);
    cudaGetSymbolAddress((void**)&p_proj, g_proj);
    cudaGetSymbolAddress((void**)&p_vpg,  g_vpg);
    cudaGetSymbolAddress((void**)&p_feat, g_feat);
    cudaGetSymbolAddress((void**)&p_ptg,  g_ptg);

    k_ln_s<<<LL,256>>>(s, ln_s_w, ln_s_b);
    k_premix<<<11,256>>>(ln_z_w, ln_z_b, Wpb, Wpo);
    k_wcat<<<(CS*NPROJ)/256,256>>>(Wq, Wk, Wv, Wq_pts, Wk_pts, Wv_pts);
    k_zpass<<<(LL*LL)/256,256>>>(z);
    k_sgemm2<<<dim3(NPROJ/64, LL/64),256>>>(p_sln, p_wcat, nullptr, nullptr, p_proj, LL, NPROJ, CS);
    k_transpose_k<<<dim3(8,24),256>>>();
    k_transform<<<LL,128>>>(R, t);
    k_logits_softmax<<<dim3(LL/4,NH),256>>>(mask, pw, attn);
    k_attn_apply<<<dim3(LL/16,NH),256>>>(attn, p_proj + OFF_V, p_feat, 32, NPROJ, FEAT, 0);
    k_attn_apply<<<dim3(LL/16,NH),256>>>(attn, p_vpg,          p_ptg,  24, 192,   192,  0);
    k_pair_out<<<LL,256>>>(attn);
    k_local<<<LL,64>>>(R, t);
    k_sgemm2<<<dim3(CS/64, LL/64),256>>>(p_feat, W_out, b_out, mask, out, LL, CS, FEAT);
}

// round 8
// speedup vs baseline: 2.2662x; 1.0690x over previous
#include <cuda_runtime.h>
#include <math.h>

#define LL 768
#define CS 256
#define CZ 128
#define NH 8
#define FEAT 544
#define NPROJ 1152
#define ATTN_OFF (LL*CS)

#define OFF_Q   0
#define OFF_K   256
#define OFF_V   512
#define OFF_QPL 768
#define OFF_KPL 864
#define OFF_VPL 960

__device__ float g_sln[LL*CS];
__device__ float g_Wcat[CS*NPROJ];
__device__ float g_proj[LL*NPROJ];
__device__ float g_kt[CS*LL];            // [c][j]
__device__ float g_qpg[LL*96];           // [i][h*12+pp]
__device__ float g_kpgt[96*LL];          // [(h*12+pp)][j]
__device__ float g_vpg[LL*192];          // [j][h*24+pp]
__device__ float g_qn[LL*NH];
__device__ float g_knt[NH*LL];
__device__ float g_pb[(long)NH*LL*LL];   // [h][i][j]
__device__ float g_pv[(long)LL*LL*32];   // [pair][h*4+d]
__device__ float g_feat[LL*FEAT];
__device__ float g_ptg[LL*192];
__device__ float g_T1[40];
__device__ float g_T0[40];
__device__ unsigned long long g_Wz[CZ*20];   // lnw-folded f32x2-packed z weights

__device__ __forceinline__ unsigned long long pk2(float lo, float hi){
    unsigned long long r; asm("mov.b64 %0,{%1,%2};":"=l"(r):"f"(lo),"f"(hi)); return r;
}
__device__ __forceinline__ void fma2(unsigned long long &d, unsigned long long a, unsigned long long b){
    asm("fma.rn.f32x2 %0, %1, %2, %0;" : "+l"(d) : "l"(a), "l"(b));
}
__device__ __forceinline__ float2 upk2(unsigned long long v){
    float2 r; asm("mov.b64 {%0,%1},%2;":"=f"(r.x),"=f"(r.y):"l"(v)); return r;
}

// ---- LN of s ----
__global__ __launch_bounds__(256) void k_ln_s(const float* __restrict__ s,
                                              const float* __restrict__ w,
                                              const float* __restrict__ b){
    int i = blockIdx.x, t = threadIdx.x;
    float x = s[i*CS + t];
    __shared__ float sh[8]; __shared__ float s_m, s_r;
    float v = x;
    #pragma unroll
    for (int o=16;o;o>>=1) v += __shfl_xor_sync(~0u,v,o);
    if ((t&31)==0) sh[t>>5]=v;
    __syncthreads();
    if (t==0){ float u=0; for(int kk=0;kk<8;kk++)u+=sh[kk]; s_m=u*(1.f/256.f); }
    __syncthreads();
    float d = x - s_m; v = d*d;
    #pragma unroll
    for (int o=16;o;o>>=1) v += __shfl_xor_sync(~0u,v,o);
    if ((t&31)==0) sh[t>>5]=v;
    __syncthreads();
    if (t==0){ float u=0; for(int kk=0;kk<8;kk++)u+=sh[kk]; s_r=rsqrtf(u*(1.f/256.f)+1e-5f); }
    __syncthreads();
    g_sln[i*CS+t] = d*s_r*w[t] + b[t];
}

// ---- premix: pack z-weights (lnw folded, f32x2) + T1/T0 fold constants ----
__global__ void k_premix(const float* __restrict__ lnw, const float* __restrict__ lnb,
                         const float* __restrict__ Wpb, const float* __restrict__ Wpo){
    int idx = blockIdx.x*256 + threadIdx.x;
    if (idx < 2560){
        int c = idx/20, np = idx%20, n = np*2;
        float w0 = lnw[c]*((n  <8)?Wpb[c*8+n  ]:Wpo[c*32+n-8]);
        float w1 = lnw[c]*((n+1<8)?Wpb[c*8+n+1]:Wpo[c*32+n-7]);
        g_Wz[idx] = pk2(w0,w1);
    } else if (idx < 2600){
        int n = idx-2560;
        float t1=0.f, t0=0.f;
        for(int c=0;c<CZ;c++){
            float wv = (n<8)?Wpb[c*8+n]:Wpo[c*32+n-8];
            t1 += lnw[c]*wv; t0 += lnb[c]*wv;
        }
        g_T1[n]=t1; g_T0[n]=t0;
    }
}

// ---- concat projection weights into [256][1152] ----
__global__ __launch_bounds__(256) void k_wcat(const float* __restrict__ Wq, const float* __restrict__ Wk,
                                              const float* __restrict__ Wv, const float* __restrict__ Wqp,
                                              const float* __restrict__ Wkp, const float* __restrict__ Wvp){
    int idx = blockIdx.x*256 + threadIdx.x;
    int k = idx/NPROJ, n = idx%NPROJ;
    float v;
    if      (n < 256)  v = Wq [k*256 + n];
    else if (n < 512)  v = Wk [k*256 + n-256];
    else if (n < 768)  v = Wv [k*256 + n-512];
    else if (n < 864)  v = Wqp[k*96  + n-768];
    else if (n < 960)  v = Wkp[k*96  + n-864];
    else               v = Wvp[k*192 + n-960];
    g_Wcat[idx] = v;
}

// ---- high-throughput SGEMM: C[M,N] = A[M,K] @ W[K,N] (+bias)(*mask) ----
__global__ __launch_bounds__(256) void k_sgemm2(const float* __restrict__ A,
                                                const float* __restrict__ W,
                                                const float* __restrict__ bias,
                                                const float* __restrict__ msk,
                                                float* __restrict__ C,
                                                int M, int N, int K){
    __shared__ float As[16][68], Bs[16][68];
    int tid = threadIdx.x;
    int tx = tid&15, ty = tid>>4;
    const float* Ab = A + (long)(blockIdx.y*64)*K;
    const float* Wb = W + blockIdx.x*64;
    float acc[4][4];
    #pragma unroll
    for(int u=0;u<4;u++)
        #pragma unroll
        for(int w2=0;w2<4;w2++) acc[u][w2]=0.f;

    int ar = tid>>2, ak = (tid&3)*4;
    int bk = tid>>4, bn = (tid&15)*4;
    float4 a4 = *(const float4*)&Ab[ar*K + ak];
    float4 b4 = *(const float4*)&Wb[(long)bk*N + bn];

    for(int k0=0;k0<K;k0+=16){
        As[ak+0][ar]=a4.x; As[ak+1][ar]=a4.y; As[ak+2][ar]=a4.z; As[ak+3][ar]=a4.w;
        *(float4*)&Bs[bk][bn]=b4;
        __syncthreads();
        if (k0+16 < K){
            a4 = *(const float4*)&Ab[ar*K + k0+16 + ak];
            b4 = *(const float4*)&Wb[(long)(k0+16+bk)*N + bn];
        }
        #pragma unroll
        for(int kk=0;kk<16;kk++){
            float4 av=*(const float4*)&As[kk][ty*4];
            float4 bv=*(const float4*)&Bs[kk][tx*4];
            float aa[4]={av.x,av.y,av.z,av.w};
            float bb[4]={bv.x,bv.y,bv.z,bv.w};
            #pragma unroll
            for(int u=0;u<4;u++)
                #pragma unroll
                for(int w2=0;w2<4;w2++) acc[u][w2] += aa[u]*bb[w2];
        }
        __syncthreads();
    }
    int gm0 = blockIdx.y*64 + ty*4, gn0 = blockIdx.x*64 + tx*4;
    #pragma unroll
    for(int u=0;u<4;u++){
        int gm = gm0+u;
        float mv = msk ? msk[gm] : 1.f;
        #pragma unroll
        for(int w2=0;w2<4;w2++){
            int gn = gn0+w2;
            float vv = acc[u][w2];
            if (bias) vv += bias[gn];
            C[(long)gm*N+gn] = vv*mv;
        }
    }
}

// ---- transpose k -> [c][j] ----
__global__ __launch_bounds__(256) void k_transpose_k(){
    __shared__ float tile[32][33];
    int c0=blockIdx.x*32, j0=blockIdx.y*32;
    int tx=threadIdx.x&31, ty=threadIdx.x>>5;
    for(int r=ty;r<32;r+=8) tile[r][tx]=g_proj[(j0+r)*NPROJ + OFF_K + c0+tx];
    __syncthreads();
    for(int r=ty;r<32;r+=8) g_kt[(c0+r)*LL+j0+tx]=tile[tx][r];
}

// ---- rigid transform of points + norms ----
__global__ __launch_bounds__(128) void k_transform(const float* __restrict__ R,
                                                   const float* __restrict__ t){
    int i=blockIdx.x, tid=threadIdx.x;
    __shared__ float Rl[9], tl[3];
    if(tid<9) Rl[tid]=R[i*9+tid];
    if(tid<3) tl[tid]=t[i*3+tid];
    __syncthreads();
    if (tid<32){
        const float* src = g_proj + i*NPROJ + OFF_QPL + tid*3;
        float p0=src[0], p1=src[1], p2=src[2];
        float gx=Rl[0]*p0+Rl[1]*p1+Rl[2]*p2+tl[0];
        float gy=Rl[3]*p0+Rl[4]*p1+Rl[5]*p2+tl[1];
        float gz=Rl[6]*p0+Rl[7]*p1+Rl[8]*p2+tl[2];
        g_qpg[i*96+tid*3]=gx; g_qpg[i*96+tid*3+1]=gy; g_qpg[i*96+tid*3+2]=gz;
        float sq=gx*gx+gy*gy+gz*gz;
        sq += __shfl_xor_sync(~0u,sq,1); sq += __shfl_xor_sync(~0u,sq,2);
        if((tid&3)==0) g_qn[i*NH+(tid>>2)]=sq;
    } else if (tid<64){
        int idx=tid-32;
        const float* src = g_proj + i*NPROJ + OFF_KPL + idx*3;
        float p0=src[0], p1=src[1], p2=src[2];
        float gx=Rl[0]*p0+Rl[1]*p1+Rl[2]*p2+tl[0];
        float gy=Rl[3]*p0+Rl[4]*p1+Rl[5]*p2+tl[1];
        float gz=Rl[6]*p0+Rl[7]*p1+Rl[8]*p2+tl[2];
        g_kpgt[(idx*3+0)*LL+i]=gx; g_kpgt[(idx*3+1)*LL+i]=gy; g_kpgt[(idx*3+2)*LL+i]=gz;
        float sq=gx*gx+gy*gy+gz*gz;
        sq += __shfl_xor_sync(~0u,sq,1); sq += __shfl_xor_sync(~0u,sq,2);
        if((idx&3)==0) g_knt[(idx>>2)*LL+i]=sq;
    } else {
        int idx=tid-64;
        const float* src = g_proj + i*NPROJ + OFF_VPL + idx*3;
        float p0=src[0], p1=src[1], p2=src[2];
        g_vpg[i*192+idx*3+0]=Rl[0]*p0+Rl[1]*p1+Rl[2]*p2+tl[0];
        g_vpg[i*192+idx*3+1]=Rl[3]*p0+Rl[4]*p1+Rl[5]*p2+tl[1];
        g_vpg[i*192+idx*3+2]=Rl[6]*p0+Rl[7]*p1+Rl[8]*p2+tl[2];
    }
}

// ---- z pass: LN folded, z read once -> pair_bias + pair_v ----
__global__ __launch_bounds__(256) void k_zpass(const float* __restrict__ z){
    __shared__ __align__(16) float U[256*41];       // union: Zs[16][264] then Os[256][41]
    __shared__ __align__(16) unsigned long long Ws[16][24];  // 4 groups of 5 ull, stride 6
    __shared__ float s_mean[256], s_rstd[256], T1s[40], T0s[40];
    float* Zs = U;
    float (*Os)[41] = (float(*)[41])U;
    int tid=threadIdx.x;
    long pair0=(long)blockIdx.x*256;
    if(tid<40){ T1s[tid]=g_T1[tid]; T0s[tid]=g_T0[tid]; }

    int rbase = (tid&63)*4;
    int ty = tid>>6;
    unsigned long long acc2[4][5];
    #pragma unroll
    for(int m=0;m<4;m++)
        #pragma unroll
        for(int n=0;n<5;n++) acc2[m][n]=0ull;

    int rq = tid>>2, kq = tid&3;
    float sums[4]={0,0,0,0}, sqs[4]={0,0,0,0};
    float4 pf[4];
    #pragma unroll
    for(int i=0;i<4;i++) pf[i] = *(const float4*)&z[(pair0+rq+64*i)*CZ + kq*4];

    for(int k0=0;k0<CZ;k0+=16){
        #pragma unroll
        for(int i=0;i<4;i++){
            float4 v=pf[i];
            sums[i]+=v.x+v.y+v.z+v.w;
            sqs[i]+=v.x*v.x+v.y*v.y+v.z*v.z+v.w*v.w;
            int row=rq+64*i, kkb=kq*4;
            Zs[(kkb+0)*264 + (row ^ (((kkb+0)&7)<<2))]=v.x;
            Zs[(kkb+1)*264 + (row ^ (((kkb+1)&7)<<2))]=v.y;
            Zs[(kkb+2)*264 + (row ^ (((kkb+2)&7)<<2))]=v.z;
            Zs[(kkb+3)*264 + (row ^ (((kkb+3)&7)<<2))]=v.w;
        }
        {   // stage 16x20 weights into 6-stride padded groups
            int l0=tid, l1=tid+256;
            int kk0=l0>>5, np0=l0&31;
            if(np0<20) Ws[kk0][(np0/5)*6 + (np0%5)]=g_Wz[(k0+kk0)*20+np0];
            int kk1=l1>>5, np1=l1&31;
            if(np1<20) Ws[kk1][(np1/5)*6 + (np1%5)]=g_Wz[(k0+kk1)*20+np1];
        }
        __syncthreads();
        if(k0+16<CZ){
            #pragma unroll
            for(int i=0;i<4;i++) pf[i]=*(const float4*)&z[(pair0+rq+64*i)*CZ + k0+16 + kq*4];
        }
        #pragma unroll
        for(int kk=0;kk<16;kk++){
            float4 z4 = *(const float4*)&Zs[kk*264 + (rbase ^ ((kk&7)<<2))];
            unsigned long long zp0=pk2(z4.x,z4.x), zp1=pk2(z4.y,z4.y);
            unsigned long long zp2=pk2(z4.z,z4.z), zp3=pk2(z4.w,z4.w);
            const unsigned long long* wrow=&Ws[kk][ty*6];
            ulonglong2 wab = *(const ulonglong2*)(wrow);
            ulonglong2 wcd = *(const ulonglong2*)(wrow+2);
            unsigned long long we = wrow[4];
            unsigned long long wv[5]={wab.x,wab.y,wcd.x,wcd.y,we};
            #pragma unroll
            for(int nn=0;nn<5;nn++){
                fma2(acc2[0][nn],zp0,wv[nn]);
                fma2(acc2[1][nn],zp1,wv[nn]);
                fma2(acc2[2][nn],zp2,wv[nn]);
                fma2(acc2[3][nn],zp3,wv[nn]);
            }
        }
        __syncthreads();
    }
    #pragma unroll
    for(int i=0;i<4;i++){
        sums[i]+=__shfl_xor_sync(~0u,sums[i],1); sums[i]+=__shfl_xor_sync(~0u,sums[i],2);
        sqs[i] +=__shfl_xor_sync(~0u,sqs[i],1);  sqs[i] +=__shfl_xor_sync(~0u,sqs[i],2);
    }
    if(kq==0){
        #pragma unroll
        for(int i=0;i<4;i++){
            float m=sums[i]*(1.f/128.f);
            s_mean[rq+64*i]=m;
            s_rstd[rq+64*i]=rsqrtf(sqs[i]*(1.f/128.f)-m*m+1e-5f);
        }
    }
    __syncthreads();
    #pragma unroll
    for(int rr=0;rr<4;rr++){
        int r=rbase+rr;
        float rs=s_rstd[r], mn=s_mean[r];
        #pragma unroll
        for(int nn=0;nn<5;nn++){
            float2 a=upk2(acc2[rr][nn]);
            int n=ty*10+nn*2;
            Os[r][n]  =rs*(a.x-mn*T1s[n])  +T0s[n];
            Os[r][n+1]=rs*(a.y-mn*T1s[n+1])+T0s[n+1];
        }
    }
    __syncthreads();
    for(int l=tid;l<2048;l+=256){
        int hh=l>>8, r=l&255;
        long p=pair0+r; int i=(int)(p/LL), j=(int)(p%LL);
        g_pb[((long)hh*LL+i)*LL+j]=Os[r][hh];
    }
    for(int l=tid;l<8192;l+=256){
        int r=l>>5, o=l&31;
        g_pv[(pair0+r)*32+o]=Os[r][8+o];
    }
}

// ---- fused logits + softmax -> attn (direct to d_out) ----
__global__ __launch_bounds__(256) void k_logits_softmax(const float* __restrict__ mask,
                                                        const float* __restrict__ pweights,
                                                        float* __restrict__ attn){
    int h=blockIdx.y, i0=blockIdx.x*4, tid=threadIdx.x;
    __shared__ float qv[4][32], qp[4][12], qnv[4], mi[4], red[8][4], bmax[4], brcp[4], s_pw;
    if(tid<128){ int ii=tid>>5, c=tid&31; qv[ii][c]=g_proj[(i0+ii)*NPROJ + OFF_Q + h*32+c]; }
    else if(tid<176){ int l=tid-128, ii=l/12, pp=l%12; qp[ii][pp]=g_qpg[(i0+ii)*96+h*12+pp]; }
    else if(tid<180){ int ii=tid-176; qnv[ii]=g_qn[(i0+ii)*NH+h]; mi[ii]=mask[i0+ii]; }
    else if(tid==180){ float xw=pweights[h]; s_pw=0.5f*log1pf(expf(xw)); }
    __syncthreads();

    float lv[3][4];
    const float invs = 0.17677669529663687f;
    #pragma unroll
    for(int jj=0;jj<3;jj++){
        int j=jj*256+tid;
        float sl[4]={0,0,0,0};
        const float* kt = g_kt + h*32*LL + j;
        #pragma unroll
        for(int c=0;c<32;c++){
            float kc=kt[c*LL];
            sl[0]+=qv[0][c]*kc; sl[1]+=qv[1][c]*kc; sl[2]+=qv[2][c]*kc; sl[3]+=qv[3][c]*kc;
        }
        float pd[4]={0,0,0,0};
        const float* kp = g_kpgt + h*12*LL + j;
        #pragma unroll
        for(int pp=0;pp<12;pp++){
            float kc=kp[pp*LL];
            pd[0]+=qp[0][pp]*kc; pd[1]+=qp[1][pp]*kc; pd[2]+=qp[2][pp]*kc; pd[3]+=qp[3][pp]*kc;
        }
        float knj=g_knt[h*LL+j], mj=mask[j];
        const float* pbp = g_pb + ((long)h*LL+i0)*LL + j;
        #pragma unroll
        for(int ii=0;ii<4;ii++){
            float lg = sl[ii]*invs + pbp[(long)ii*LL] - s_pw*(qnv[ii]+knj-2.f*pd[ii]);
            if (mi[ii]*mj==0.f) lg=-1e9f;
            lv[jj][ii]=lg;
        }
    }
    #pragma unroll
    for(int ii=0;ii<4;ii++){
        float m=fmaxf(fmaxf(lv[0][ii],lv[1][ii]),lv[2][ii]);
        #pragma unroll
        for(int o=16;o;o>>=1) m=fmaxf(m,__shfl_xor_sync(~0u,m,o));
        if((tid&31)==0) red[tid>>5][ii]=m;
    }
    __syncthreads();
    if(tid<4){ float m=red[0][tid]; for(int w=1;w<8;w++)m=fmaxf(m,red[w][tid]); bmax[tid]=m; }
    __syncthreads();
    float ev[3][4], sm[4]={0,0,0,0};
    #pragma unroll
    for(int jj=0;jj<3;jj++)
        #pragma unroll
        for(int ii=0;ii<4;ii++){ float e=__expf(lv[jj][ii]-bmax[ii]); ev[jj][ii]=e; sm[ii]+=e; }
    __syncthreads();
    #pragma unroll
    for(int ii=0;ii<4;ii++){
        float s=sm[ii];
        #pragma unroll
        for(int o=16;o;o>>=1) s+=__shfl_xor_sync(~0u,s,o);
        if((tid&31)==0) red[tid>>5][ii]=s;
    }
    __syncthreads();
    if(tid<4){ float s=0; for(int w=0;w<8;w++)s+=red[w][tid]; brcp[tid]=1.f/s; }
    __syncthreads();
    #pragma unroll
    for(int jj=0;jj<3;jj++){
        int j=jj*256+tid;
        #pragma unroll
        for(int ii=0;ii<4;ii++)
            attn[((long)h*LL+i0+ii)*LL+j]=ev[jj][ii]*brcp[ii];
    }
}

// ---- fused attn @ [V | v_pts_global]: 56 output cols per head ----
__global__ __launch_bounds__(256) void k_attn_fused(const float* __restrict__ attn,
                                                    const float* __restrict__ V1,
                                                    const float* __restrict__ V2){
    int h=blockIdx.y, i0=blockIdx.x*16, tid=threadIdx.x;
    __shared__ float As[16][33], Vs[32][64];
    int n=tid&63, iw=tid>>6;   // rows iw, iw+4, iw+8, iw+12
    float a0=0.f,a1=0.f,a2=0.f,a3=0.f;
    for(int j0=0;j0<LL;j0+=32){
        for(int l=tid;l<512;l+=256){
            int r=l>>5, jj=l&31;
            As[r][jj]=attn[((long)h*LL+i0+r)*LL+j0+jj];
        }
        for(int l=tid;l<2048;l+=256){
            int r=l>>6, c=l&63;
            float v;
            if (c<32)      v = V1[(long)(j0+r)*NPROJ + h*32 + c];
            else if (c<56) v = V2[(long)(j0+r)*192   + h*24 + (c-32)];
            else           v = 0.f;
            Vs[r][c]=v;
        }
        __syncthreads();
        #pragma unroll
        for(int jj=0;jj<32;jj++){
            float vv=Vs[jj][n];
            a0+=As[iw][jj]*vv; a1+=As[iw+4][jj]*vv;
            a2+=As[iw+8][jj]*vv; a3+=As[iw+12][jj]*vv;
        }
        __syncthreads();
    }
    if (n<32){
        g_feat[(i0+iw)   *FEAT + h*32+n]=a0;
        g_feat[(i0+iw+4) *FEAT + h*32+n]=a1;
        g_feat[(i0+iw+8) *FEAT + h*32+n]=a2;
        g_feat[(i0+iw+12)*FEAT + h*32+n]=a3;
    } else if (n<56){
        int c=n-32;
        g_ptg[(i0+iw)   *192 + h*24+c]=a0;
        g_ptg[(i0+iw+4) *192 + h*24+c]=a1;
        g_ptg[(i0+iw+8) *192 + h*24+c]=a2;
        g_ptg[(i0+iw+12)*192 + h*24+c]=a3;
    }
}

// ---- pair_out ----
__global__ __launch_bounds__(256) void k_pair_out(const float* __restrict__ attn){
    int i=blockIdx.x, tid=threadIdx.x;
    int o=tid&31, jw=tid>>5, h=o>>2;
    float acc=0.f;
    for(int j=jw;j<LL;j+=8)
        acc += attn[((long)h*LL+i)*LL+j]*g_pv[((long)i*LL+j)*32+o];
    __shared__ float red[8][32];
    red[jw][o]=acc;
    __syncthreads();
    if(tid<32){
        float s=0; for(int w=0;w<8;w++)s+=red[w][tid];
        g_feat[i*FEAT+512+tid]=s;
    }
}

// ---- back to local frame + norms ----
__global__ __launch_bounds__(64) void k_local(const float* __restrict__ R,
                                              const float* __restrict__ t){
    int i=blockIdx.x, tid=threadIdx.x;
    __shared__ float Rl[9], tl[3];
    if(tid<9) Rl[tid]=R[i*9+tid];
    if(tid<3) tl[tid]=t[i*3+tid];
    __syncthreads();
    float gx=g_ptg[i*192+tid*3]  -tl[0];
    float gy=g_ptg[i*192+tid*3+1]-tl[1];
    float gz=g_ptg[i*192+tid*3+2]-tl[2];
    float lx=Rl[0]*gx+Rl[3]*gy+Rl[6]*gz;
    float ly=Rl[1]*gx+Rl[4]*gy+Rl[7]*gz;
    float lz=Rl[2]*gx+Rl[5]*gy+Rl[8]*gz;
    g_feat[i*FEAT+256+tid*3]  =lx;
    g_feat[i*FEAT+256+tid*3+1]=ly;
    g_feat[i*FEAT+256+tid*3+2]=lz;
    g_feat[i*FEAT+448+tid]=sqrtf(lx*lx+ly*ly+lz*lz+1e-8f);
}

extern "C" void kernel_launch(void* const* d_in, const int* in_sizes, int n_in,
                              void* d_out, int out_size){
    const float* s      =(const float*)d_in[0];
    const float* z      =(const float*)d_in[1];
    const float* R      =(const float*)d_in[2];
    const float* t      =(const float*)d_in[3];
    const float* mask   =(const float*)d_in[4];
    const float* ln_s_w =(const float*)d_in[5];
    const float* ln_s_b =(const float*)d_in[6];
    const float* ln_z_w =(const float*)d_in[7];
    const float* ln_z_b =(const float*)d_in[8];
    const float* Wq     =(const float*)d_in[9];
    const float* Wk     =(const float*)d_in[10];
    const float* Wv     =(const float*)d_in[11];
    const float* Wpb    =(const float*)d_in[12];
    const float* Wq_pts =(const float*)d_in[13];
    const float* Wk_pts =(const float*)d_in[14];
    const float* Wv_pts =(const float*)d_in[15];
    const float* pw     =(const float*)d_in[16];
    const float* Wpo    =(const float*)d_in[17];
    const float* W_out  =(const float*)d_in[18];
    const float* b_out  =(const float*)d_in[19];
    float* out  = (float*)d_out;
    float* attn = out + ATTN_OFF;

    float *p_sln,*p_wcat,*p_proj,*p_vpg,*p_feat;
    cudaGetSymbolAddress((void**)&p_sln,  g_sln);
    cudaGetSymbolAddress((void**)&p_wcat, g_Wcat);
    cudaGetSymbolAddress((void**)&p_proj, g_proj);
    cudaGetSymbolAddress((void**)&p_vpg,  g_vpg);
    cudaGetSymbolAddress((void**)&p_feat, g_feat);

    // side stream + events for fork/join concurrency inside graph capture
    static cudaStream_t sB = nullptr;
    static cudaEvent_t evFork = nullptr, evJoin = nullptr;
    if (sB == nullptr){
        cudaStreamCreateWithFlags(&sB, cudaStreamNonBlocking);
        cudaEventCreateWithFlags(&evFork, cudaEventDisableTiming);
        cudaEventCreateWithFlags(&evJoin, cudaEventDisableTiming);
    }

    // fork: branch B (projection chain) runs concurrently with branch A (z pass)
    cudaEventRecord(evFork, 0);
    cudaStreamWaitEvent(sB, evFork, 0);

    // branch B on sB
    k_ln_s<<<LL,256,0,sB>>>(s, ln_s_w, ln_s_b);
    k_wcat<<<(CS*NPROJ)/256,256,0,sB>>>(Wq, Wk, Wv, Wq_pts, Wk_pts, Wv_pts);
    k_sgemm2<<<dim3(NPROJ/64, LL/64),256,0,sB>>>(p_sln, p_wcat, nullptr, nullptr, p_proj, LL, NPROJ, CS);
    k_transpose_k<<<dim3(8,24),256,0,sB>>>();
    k_transform<<<LL,128,0,sB>>>(R, t);
    cudaEventRecord(evJoin, sB);

    // branch A on main stream
    k_premix<<<11,256>>>(ln_z_w, ln_z_b, Wpb, Wpo);
    k_zpass<<<(LL*LL)/256,256>>>(z);

    // join
    cudaStreamWaitEvent(0, evJoin, 0);

    k_logits_softmax<<<dim3(LL/4,NH),256>>>(mask, pw, attn);
    k_attn_fused<<<dim3(LL/16,NH),256>>>(attn, p_proj + OFF_V, p_vpg);
    k_pair_out<<<LL,256>>>(attn);
    k_local<<<LL,64>>>(R, t);
    k_sgemm2<<<dim3(CS/64, LL/64),256>>>(p_feat, W_out, b_out, mask, out, LL, CS, FEAT);
}